// round 11
// baseline (speedup 1.0000x reference)
#include <cuda_runtime.h>
#include <cuda_bf16.h>
#include <cstdint>

// Problem constants (fixed by the dataset)
#define BB   1024
#define TT   256
#define INDIM 128
#define HH   128
#define GG   384      // 3*H
#define HOR  24

// ---------------- scratch (device globals; no allocations allowed) ----------
__device__ float g_gx[(size_t)TT * BB * GG];        // 384 MB: x@w_i + b, [t][b][g]
__device__ float g_ys[(size_t)TT * BB * HH];        // 128 MB: hidden states, [t][b][j]
__device__ float g_W2[(size_t)TT * HH * HOR];       // 3 MB: folded weights, [t][j][p]
__device__ float g_bias_part[TT * HOR];
__device__ float g_final_bias[HOR];
__device__ __nv_bfloat16 g_whi[GG * INDIM];         // w_i^T hi, [n][k]
__device__ __nv_bfloat16 g_wlo[GG * INDIM];         // w_i^T lo, [n][k]

// ---------------- packed f32x2 helpers (bit-exact vs 2x scalar) -------------
typedef unsigned long long u64;

__device__ __forceinline__ u64 pack2(float lo, float hi) {
    u64 r; asm("mov.b64 %0, {%1, %2};" : "=l"(r) : "f"(lo), "f"(hi)); return r;
}
__device__ __forceinline__ u64 dup2(float v) {
    u64 r; asm("mov.b64 %0, {%1, %1};" : "=l"(r) : "f"(v)); return r;
}
__device__ __forceinline__ void unpack2(u64 v, float& lo, float& hi) {
    asm("mov.b64 {%0, %1}, %2;" : "=f"(lo), "=f"(hi) : "l"(v));
}
__device__ __forceinline__ void ffma2(u64& d, u64 a, u64 b) {
    asm("fma.rn.f32x2 %0, %1, %2, %0;" : "+l"(d) : "l"(a), "l"(b));
}
__device__ __forceinline__ void fadd2(u64& d, u64 a) {
    asm("add.rn.f32x2 %0, %0, %1;" : "+l"(d) : "l"(a));
}
__device__ __forceinline__ u64 shfl_xor_u64(u64 v, int m) {
    uint32_t lo = (uint32_t)v, hi = (uint32_t)(v >> 32);
    lo = __shfl_xor_sync(0xffffffffu, lo, m);
    hi = __shfl_xor_sync(0xffffffffu, hi, m);
    return ((u64)hi << 32) | (u64)lo;
}

// ---------------- mma.sync / ldmatrix helpers (sm_100 baseline ISA) ----------
__device__ __forceinline__ uint32_t smem_u32(const void* p) {
    uint32_t a;
    asm("{ .reg .u64 t; cvta.to.shared.u64 t, %1; cvt.u32.u64 %0, t; }" : "=r"(a) : "l"(p));
    return a;
}
__device__ __forceinline__ void ldsm_x4(uint32_t* r, uint32_t addr) {
    asm volatile("ldmatrix.sync.aligned.m8n8.x4.shared.b16 {%0,%1,%2,%3}, [%4];"
                 : "=r"(r[0]), "=r"(r[1]), "=r"(r[2]), "=r"(r[3]) : "r"(addr));
}
__device__ __forceinline__ void mma_bf16(float* d, const uint32_t* a,
                                         uint32_t b0, uint32_t b1) {
    asm volatile(
        "mma.sync.aligned.m16n8k16.row.col.f32.bf16.bf16.f32 "
        "{%0,%1,%2,%3}, {%4,%5,%6,%7}, {%8,%9}, {%0,%1,%2,%3};"
        : "+f"(d[0]), "+f"(d[1]), "+f"(d[2]), "+f"(d[3])
        : "r"(a[0]), "r"(a[1]), "r"(a[2]), "r"(a[3]), "r"(b0), "r"(b1));
}
// swizzled byte offset for bf16 tile [row][col], 256B rows, 16B chunks
__device__ __forceinline__ uint32_t swz(int row, int c16) {
    return (uint32_t)(row * 256 + ((c16 ^ (row & 7)) << 4));
}

// ---------------- activation helpers ----------------------------------------
__device__ __forceinline__ float sigmoid_f(float x) {
    return 1.0f / (1.0f + __expf(-x));
}
__device__ __forceinline__ float tanh_f(float x) {
    float ax = fabsf(x);
    float e  = __expf(2.0f * ax);
    float r  = 1.0f - 2.0f / (e + 1.0f);
    return copysignf(r, x);
}

// ============================================================================
// Kernel 1: fold  W2_t = mlp_w @ (fc_w_t @ out_w)  and bias partial per t.
// ============================================================================
__global__ void __launch_bounds__(256) w2_kernel(
    const float* __restrict__ mlp_w,   // [128,512]
    const float* __restrict__ mlp_b,   // [512]
    const float* __restrict__ fc_w,    // [131072,128]
    const float* __restrict__ out_w)   // [128,24]
{
    extern __shared__ float sm[];
    float* ows    = sm;
    float* P      = sm + 3072;
    float* rowbuf = sm + 3072 + 12288;
    const int tid  = threadIdx.x;
    const int t    = blockIdx.x;
    const int warp = tid >> 5;
    const int lane = tid & 31;

    for (int i = tid; i < HH * HOR; i += 256) ows[i] = out_w[i];
    __syncthreads();

    const float* fcb = fc_w + (size_t)t * 512 * HH;
    for (int j = warp; j < 512; j += 8) {
        float4 v = ((const float4*)(fcb + (size_t)j * HH))[lane];
        ((float4*)(rowbuf + warp * 128))[lane] = v;
        __syncwarp();
        if (lane < HOR) {
            const float* rb = rowbuf + warp * 128;
            float acc = 0.0f;
            #pragma unroll 4
            for (int k = 0; k < 128; k++) acc = fmaf(rb[k], ows[k * HOR + lane], acc);
            P[j * HOR + lane] = acc;
        }
        __syncwarp();
    }
    __syncthreads();

    if (warp == 0 && lane < HOR) {
        float acc = 0.0f;
        for (int j = 0; j < 512; j++) acc = fmaf(mlp_b[j], P[j * HOR + lane], acc);
        g_bias_part[t * HOR + lane] = acc;
    }

    const int i  = tid & 127;
    const int p0 = (tid >> 7) * 12;
    float acc[12];
    #pragma unroll
    for (int q = 0; q < 12; q++) acc[q] = 0.0f;
    const float* mw = mlp_w + (size_t)i * 512;
    for (int j = 0; j < 512; j++) {
        float m = mw[j];
        const float* pr = P + j * HOR + p0;
        #pragma unroll
        for (int q = 0; q < 12; q++) acc[q] = fmaf(m, pr[q], acc[q]);
    }
    float* dst = g_W2 + ((size_t)t * HH + i) * HOR + p0;
    #pragma unroll
    for (int q = 0; q < 12; q++) dst[q] = acc[q];
}

// ============================================================================
// Kernel 2: final bias = sum_t bias_part + fc_b@out_w + out_b
// ============================================================================
__global__ void bias_final_kernel(const float* __restrict__ fc_b,
                                  const float* __restrict__ out_w,
                                  const float* __restrict__ out_b)
{
    int p = threadIdx.x;
    if (p >= HOR) return;
    float s = out_b[p];
    for (int t = 0; t < TT; t++) s += g_bias_part[t * HOR + p];
    for (int o = 0; o < HH; o++) s = fmaf(fc_b[o], out_w[o * HOR + p], s);
    g_final_bias[p] = s;
}

// ============================================================================
// Kernel 2b: split w_i into bf16 hi/lo, transposed to [n][k] (B operand).
// ============================================================================
__global__ void wsplit_kernel(const float* __restrict__ w_i)  // [128k][384n]
{
    int n = blockIdx.x;     // 0..383
    int k = threadIdx.x;    // 0..127
    float v = w_i[(size_t)k * GG + n];
    __nv_bfloat16 h = __float2bfloat16(v);
    float lo = v - __bfloat162float(h);
    g_whi[n * INDIM + k] = h;
    g_wlo[n * INDIM + k] = __float2bfloat16(lo);
}

// ============================================================================
// Kernel 3 (v8): gx = x @ w_i + b via mma.sync bf16 3-term split.
// CTA = 64 rows x 1 gate (N=128), K=128 -> 96KB smem -> 2 CTAs/SM.
// 8 warps tiled 2(m) x 4(n): warp tile m32 x n32. 3 passes x 8 K-steps.
// ============================================================================
#define GXM_A_HI  0
#define GXM_A_LO  16384
#define GXM_B_HI  32768
#define GXM_B_LO  65536
#define GXM_SMEM  98304

__global__ void __launch_bounds__(256, 2) gx_mma_kernel(
    const float* __restrict__ x,     // [B][T][128] == [m][128]
    const float* __restrict__ bvec)  // [384]
{
    extern __shared__ char smemc[];
    const int tid  = threadIdx.x;
    const int wid  = tid >> 5;
    const int lane = tid & 31;
    const int gate = blockIdx.x % 3;
    const int m0g  = (blockIdx.x / 3) * 64;
    uint32_t sbase = smem_u32(smemc);

    // ---- stage A (64 rows): read x fp32, split bf16 hi/lo, store swizzled ----
    {
        int row = tid >> 2, q = tid & 3;   // row 0..63, col-quarter (32 cols)
        const float4* xr = (const float4*)(x + (size_t)(m0g + row) * INDIM + q * 32);
        #pragma unroll
        for (int u = 0; u < 4; u++) {
            float4 a = xr[2 * u], b = xr[2 * u + 1];
            float f[8] = {a.x, a.y, a.z, a.w, b.x, b.y, b.z, b.w};
            uint32_t hi[4], lo[4];
            #pragma unroll
            for (int p = 0; p < 4; p++) {
                __nv_bfloat162 h = __floats2bfloat162_rn(f[2*p], f[2*p+1]);
                hi[p] = *(uint32_t*)&h;
                float l0 = f[2*p]     - __bfloat162float(h.x);
                float l1 = f[2*p + 1] - __bfloat162float(h.y);
                __nv_bfloat162 l = __floats2bfloat162_rn(l0, l1);
                lo[p] = *(uint32_t*)&l;
            }
            uint32_t o = swz(row, q * 4 + u);
            *(uint4*)(smemc + GXM_A_HI + o) = make_uint4(hi[0], hi[1], hi[2], hi[3]);
            *(uint4*)(smemc + GXM_A_LO + o) = make_uint4(lo[0], lo[1], lo[2], lo[3]);
        }
    }
    // ---- stage B (128 n-rows): pre-split weights (L2), store swizzled ----
    {
        int row = tid >> 1, half = tid & 1;     // row = n index
        size_t src = (size_t)(gate * 128 + row) * INDIM + half * 64;
        const uint4* bh = (const uint4*)(g_whi + src);
        const uint4* bl = (const uint4*)(g_wlo + src);
        #pragma unroll
        for (int u = 0; u < 8; u++) {
            uint32_t o = swz(row, half * 8 + u);
            *(uint4*)(smemc + GXM_B_HI + o) = bh[u];
            *(uint4*)(smemc + GXM_B_LO + o) = bl[u];
        }
    }
    __syncthreads();

    // warp tile: m-rows [m0w, m0w+32), n-cols [n0w, n0w+32)
    const int m0w = (wid & 1) * 32;
    const int n0w = (wid >> 1) * 32;
    const int lr  = lane & 15;          // ldmatrix row-within-16
    const int lc  = lane >> 4;          // ldmatrix chunk select (k8 halves)

    float acc[2][4][4];
    #pragma unroll
    for (int mi = 0; mi < 2; mi++)
        #pragma unroll
        for (int nt = 0; nt < 4; nt++)
            #pragma unroll
            for (int q = 0; q < 4; q++) acc[mi][nt][q] = 0.0f;

    #pragma unroll 1
    for (int pass = 0; pass < 3; pass++) {
        const uint32_t aBase = sbase + ((pass == 2) ? GXM_A_LO : GXM_A_HI);
        const uint32_t bBase = sbase + ((pass == 1) ? GXM_B_LO : GXM_B_HI);
        #pragma unroll
        for (int s = 0; s < 8; s++) {
            const int c16 = 2 * s + lc;
            // A fragments: tiles at m0w, m0w+16
            uint32_t a0[4], a1[4];
            {
                int r0 = m0w + lr;
                ldsm_x4(a0, aBase + swz(r0, c16));
                ldsm_x4(a1, aBase + swz(r0 + 16, c16));
            }
            // B fragments: 2 x (n16 k16) covering n0w..n0w+31
            uint32_t b[2][4];
            #pragma unroll
            for (int q = 0; q < 2; q++) {
                int rn = n0w + q * 16 + lr;
                ldsm_x4(b[q], bBase + swz(rn, c16));
            }
            // 8 mma: 2 m-tiles x 4 n-tiles
            #pragma unroll
            for (int nt = 0; nt < 4; nt++) {
                int q = nt >> 1, sel = nt & 1;
                uint32_t bb0 = b[q][sel];       // (n-half, k0)
                uint32_t bb1 = b[q][sel + 2];   // (n-half, k8)
                mma_bf16(acc[0][nt], a0, bb0, bb1);
                mma_bf16(acc[1][nt], a1, bb0, bb1);
            }
        }
    }

    // ---- epilogue: bias + store ----
    const int colq = (lane & 3) * 2;
    #pragma unroll
    for (int nt = 0; nt < 4; nt++) {
        int c = n0w + nt * 8 + colq;
        float2 bv = *(const float2*)(bvec + gate * 128 + c);
        #pragma unroll
        for (int mi = 0; mi < 2; mi++) {
            int gm0 = m0g + m0w + 16 * mi + (lane >> 2);
            // rows gm0 and gm0+8
            #pragma unroll
            for (int h = 0; h < 2; h++) {
                int gm = gm0 + 8 * h;
                int tt = gm & 255, bb = gm >> 8;
                float2 o;
                o.x = acc[mi][nt][2 * h + 0] + bv.x;
                o.y = acc[mi][nt][2 * h + 1] + bv.y;
                *(float2*)(g_gx + ((size_t)tt * BB + bb) * GG + gate * 128 + c) = o;
            }
        }
    }
}

// ============================================================================
// Kernel 4 (v7, unchanged): recurrence. w_h in regs, deep k-split + shuffles.
// ============================================================================
__global__ void __launch_bounds__(512, 1) rec_kernel(
    const float* __restrict__ w_h)   // [128][384]
{
    __shared__ float hT[1024];    // [j][r]
    __shared__ float rhT[1024];   // [j][r]
    __shared__ float zs[1024];    // [col][r]

    const int tid = threadIdx.x;
    const int w   = tid >> 5;
    const int l   = tid & 31;
    const int b0  = blockIdx.x * 8;

    const int colA = w * 16 + 2 * (l & 7);
    const int s1   = l >> 3;
    const int rz   = 2 * s1;
    const int colB = w * 8 + 2 * (l & 3);
    const int s3   = l >> 2;
    const int jf2  = 2 * (s3 & 1) + ((s3 >> 1) & 1);
    const int rF   = 2 * jf2 + (s3 >> 2);
    const int jA   = colA - 128;

    float wzA[32], wzB[32];
    #pragma unroll
    for (int i = 0; i < 32; i++) {
        wzA[i] = __ldg(w_h + (size_t)(4 * i + s1) * GG + colA);
        wzB[i] = __ldg(w_h + (size_t)(4 * i + s1) * GG + colA + 1);
    }
    float waA[16], waB[16];
    #pragma unroll
    for (int i = 0; i < 16; i++) {
        waA[i] = __ldg(w_h + (size_t)(8 * i + s3) * GG + 256 + colB);
        waB[i] = __ldg(w_h + (size_t)(8 * i + s3) * GG + 256 + colB + 1);
    }

    for (int i = tid; i < 1024; i += 512) hT[i] = 0.0f;
    __syncthreads();

    float2 g1a, g1b;
    {
        const float* g0 = g_gx + (size_t)b0 * GG;
        g1a = *(const float2*)(g0 + (rz + 0) * GG + colA);
        g1b = *(const float2*)(g0 + (rz + 1) * GG + colA);
    }

    for (int t = 0; t < TT; t++) {
        const float* gxt = g_gx + ((size_t)t * BB + b0) * GG;
        float2 g2 = *(const float2*)(gxt + rF * GG + 256 + colB);

        u64 pA[4] = {0ULL,0ULL,0ULL,0ULL};
        u64 pB[4] = {0ULL,0ULL,0ULL,0ULL};
        #pragma unroll
        for (int i = 0; i < 32; i++) {
            const float* hp = &hT[(4 * i + s1) * 8];
            ulonglong2 h0 = *(const ulonglong2*)hp;
            ulonglong2 h1 = *(const ulonglong2*)(hp + 4);
            u64 wdA = dup2(wzA[i]);
            u64 wdB = dup2(wzB[i]);
            ffma2(pA[0], h0.x, wdA); ffma2(pA[1], h0.y, wdA);
            ffma2(pA[2], h1.x, wdA); ffma2(pA[3], h1.y, wdA);
            ffma2(pB[0], h0.x, wdB); ffma2(pB[1], h0.y, wdB);
            ffma2(pB[2], h1.x, wdB); ffma2(pB[3], h1.y, wdB);
        }
        {
            u64 tA0 = shfl_xor_u64(pA[0], 16), tA1 = shfl_xor_u64(pA[1], 16);
            u64 tA2 = shfl_xor_u64(pA[2], 16), tA3 = shfl_xor_u64(pA[3], 16);
            u64 tB0 = shfl_xor_u64(pB[0], 16), tB1 = shfl_xor_u64(pB[1], 16);
            u64 tB2 = shfl_xor_u64(pB[2], 16), tB3 = shfl_xor_u64(pB[3], 16);
            bool hiB = (s1 & 2) != 0;
            u64 kA0 = hiB ? pA[2] : pA[0], rA0 = hiB ? tA2 : tA0;
            u64 kA1 = hiB ? pA[3] : pA[1], rA1 = hiB ? tA3 : tA1;
            u64 kB0 = hiB ? pB[2] : pB[0], rB0 = hiB ? tB2 : tB0;
            u64 kB1 = hiB ? pB[3] : pB[1], rB1 = hiB ? tB3 : tB1;
            fadd2(kA0, rA0); fadd2(kA1, rA1);
            fadd2(kB0, rB0); fadd2(kB1, rB1);
            u64 uA0 = shfl_xor_u64(kA0, 8), uA1 = shfl_xor_u64(kA1, 8);
            u64 uB0 = shfl_xor_u64(kB0, 8), uB1 = shfl_xor_u64(kB1, 8);
            bool hi0 = (s1 & 1) != 0;
            u64 fA = hi0 ? kA1 : kA0, gA = hi0 ? uA1 : uA0;
            u64 fB = hi0 ? kB1 : kB0, gB = hi0 ? uB1 : uB0;
            fadd2(fA, gA); fadd2(fB, gB);

            float aA0, aA1, aB0, aB1;
            unpack2(fA, aA0, aA1);
            unpack2(fB, aB0, aB1);
            aA0 += g1a.x; aB0 += g1a.y;
            aA1 += g1b.x; aB1 += g1b.y;

            if (colA < 128) {
                float2 vA = make_float2(sigmoid_f(aA0), sigmoid_f(aA1));
                float2 vB = make_float2(sigmoid_f(aB0), sigmoid_f(aB1));
                *(float2*)&zs[(colA + 0) * 8 + rz] = vA;
                *(float2*)&zs[(colA + 1) * 8 + rz] = vB;
            } else {
                float2 hA = *(const float2*)&hT[(jA + 0) * 8 + rz];
                float2 hB = *(const float2*)&hT[(jA + 1) * 8 + rz];
                float2 oA = make_float2(sigmoid_f(aA0) * hA.x, sigmoid_f(aA1) * hA.y);
                float2 oB = make_float2(sigmoid_f(aB0) * hB.x, sigmoid_f(aB1) * hB.y);
                *(float2*)&rhT[(jA + 0) * 8 + rz] = oA;
                *(float2*)&rhT[(jA + 1) * 8 + rz] = oB;
            }
        }

        if (t + 1 < TT) {
            const float* gxn = g_gx + ((size_t)(t + 1) * BB + b0) * GG;
            g1a = *(const float2*)(gxn + (rz + 0) * GG + colA);
            g1b = *(const float2*)(gxn + (rz + 1) * GG + colA);
        }
        __syncthreads();

        u64 qA[4] = {0ULL,0ULL,0ULL,0ULL};
        u64 qB[4] = {0ULL,0ULL,0ULL,0ULL};
        #pragma unroll
        for (int i = 0; i < 16; i++) {
            const float* rp = &rhT[(8 * i + s3) * 8];
            ulonglong2 r0 = *(const ulonglong2*)rp;
            ulonglong2 r1 = *(const ulonglong2*)(rp + 4);
            u64 wdA = dup2(waA[i]);
            u64 wdB = dup2(waB[i]);
            ffma2(qA[0], r0.x, wdA); ffma2(qA[1], r0.y, wdA);
            ffma2(qA[2], r1.x, wdA); ffma2(qA[3], r1.y, wdA);
            ffma2(qB[0], r0.x, wdB); ffma2(qB[1], r0.y, wdB);
            ffma2(qB[2], r1.x, wdB); ffma2(qB[3], r1.y, wdB);
        }
        float vA, vB;
        {
            u64 tA0 = shfl_xor_u64(qA[0], 4), tA1 = shfl_xor_u64(qA[1], 4);
            u64 tA2 = shfl_xor_u64(qA[2], 4), tA3 = shfl_xor_u64(qA[3], 4);
            u64 tB0 = shfl_xor_u64(qB[0], 4), tB1 = shfl_xor_u64(qB[1], 4);
            u64 tB2 = shfl_xor_u64(qB[2], 4), tB3 = shfl_xor_u64(qB[3], 4);
            bool hiB = (s3 & 1) != 0;
            u64 kA0 = hiB ? qA[2] : qA[0], rA0 = hiB ? tA2 : tA0;
            u64 kA1 = hiB ? qA[3] : qA[1], rA1 = hiB ? tA3 : tA1;
            u64 kB0 = hiB ? qB[2] : qB[0], rB0 = hiB ? tB2 : tB0;
            u64 kB1 = hiB ? qB[3] : qB[1], rB1 = hiB ? tB3 : tB1;
            fadd2(kA0, rA0); fadd2(kA1, rA1);
            fadd2(kB0, rB0); fadd2(kB1, rB1);
            u64 uA0 = shfl_xor_u64(kA0, 8), uA1 = shfl_xor_u64(kA1, 8);
            u64 uB0 = shfl_xor_u64(kB0, 8), uB1 = shfl_xor_u64(kB1, 8);
            bool hi1 = ((s3 >> 1) & 1) != 0;
            u64 fA = hi1 ? kA1 : kA0, gA = hi1 ? uA1 : uA0;
            u64 fB = hi1 ? kB1 : kB0, gB = hi1 ? uB1 : uB0;
            fadd2(fA, gA); fadd2(fB, gB);
            float loA, hiA_, loB, hiB_;
            unpack2(fA, loA, hiA_);
            unpack2(fB, loB, hiB_);
            bool top = (s3 & 4) != 0;
            float sendA = top ? loA : hiA_;
            float sendB = top ? loB : hiB_;
            float rcvA = __shfl_xor_sync(0xffffffffu, sendA, 16);
            float rcvB = __shfl_xor_sync(0xffffffffu, sendB, 16);
            vA = (top ? hiA_ : loA) + rcvA;
            vB = (top ? hiB_ : loB) + rcvB;
        }
        {
            float z0 = zs[(colB + 0) * 8 + rF];
            float z1 = zs[(colB + 1) * 8 + rF];
            float h0 = hT[(colB + 0) * 8 + rF];
            float h1 = hT[(colB + 1) * 8 + rF];
            float hn0 = fmaf(z0, tanh_f(vA + g2.x) - h0, h0);
            float hn1 = fmaf(z1, tanh_f(vB + g2.y) - h1, h1);
            hT[(colB + 0) * 8 + rF] = hn0;
            hT[(colB + 1) * 8 + rF] = hn1;
            *(float2*)&g_ys[((size_t)t * BB + b0 + rF) * HH + colB] = make_float2(hn0, hn1);
        }
        __syncthreads();
    }
}

// ============================================================================
// Kernel 5 (unchanged): out[b,p] = sum_t sum_j ys[t,b,j]*W2[t,j,p] + bias.
// ============================================================================
__global__ void __launch_bounds__(512, 1) fc_kernel(float* __restrict__ out)
{
    __shared__ float red[8 * HOR * 4];

    const int tid = threadIdx.x;
    const int j   = tid & 127;
    const int g   = tid >> 7;
    const int b0  = blockIdx.x * 8;
    const int lane = tid & 31;
    const int jblk = (j >> 5);

    u64 acc[2][12];
    #pragma unroll
    for (int u = 0; u < 2; u++)
        #pragma unroll
        for (int q = 0; q < 12; q++) acc[u][q] = 0ULL;

    #pragma unroll 2
    for (int t = 0; t < TT; t++) {
        const float* ysp = g_ys + ((size_t)t * BB + b0 + 2 * g) * HH + j;
        float y0 = __ldg(ysp);
        float y1 = __ldg(ysp + HH);
        const ulonglong2* wp = (const ulonglong2*)(g_W2 + ((size_t)t * HH + j) * HOR);
        ulonglong2 w0 = wp[0], w1 = wp[1], w2 = wp[2],
                   w3 = wp[3], w4 = wp[4], w5 = wp[5];
        u64 wq[12] = {w0.x, w0.y, w1.x, w1.y, w2.x, w2.y,
                      w3.x, w3.y, w4.x, w4.y, w5.x, w5.y};
        u64 y0d = dup2(y0), y1d = dup2(y1);
        #pragma unroll
        for (int q = 0; q < 12; q++) {
            ffma2(acc[0][q], y0d, wq[q]);
            ffma2(acc[1][q], y1d, wq[q]);
        }
    }

    #pragma unroll
    for (int u = 0; u < 2; u++)
        #pragma unroll
        for (int q = 0; q < 12; q++) {
            fadd2(acc[u][q], shfl_xor_u64(acc[u][q], 1));
            fadd2(acc[u][q], shfl_xor_u64(acc[u][q], 2));
            fadd2(acc[u][q], shfl_xor_u64(acc[u][q], 4));
            fadd2(acc[u][q], shfl_xor_u64(acc[u][q], 8));
            fadd2(acc[u][q], shfl_xor_u64(acc[u][q], 16));
        }

    if (lane == 0) {
        #pragma unroll
        for (int u = 0; u < 2; u++) {
            int row = 2 * g + u;
            #pragma unroll
            for (int q = 0; q < 12; q++) {
                float v0, v1;
                unpack2(acc[u][q], v0, v1);
                red[(row * HOR + 2 * q + 0) * 4 + jblk] = v0;
                red[(row * HOR + 2 * q + 1) * 4 + jblk] = v1;
            }
        }
    }
    __syncthreads();

    if (tid < 8 * HOR) {
        int row = tid / HOR;
        int p   = tid - row * HOR;
        const float* pp = red + (row * HOR + p) * 4;
        float s = ((pp[0] + pp[1]) + pp[2]) + pp[3];
        out[(size_t)(b0 + row) * HOR + p] = s + g_final_bias[p];
    }
}

// ============================================================================
// launch
// ============================================================================
extern "C" void kernel_launch(void* const* d_in, const int* in_sizes, int n_in,
                              void* d_out, int out_size)
{
    const float* x     = (const float*)d_in[0];
    const float* w_i   = (const float*)d_in[1];
    const float* w_h   = (const float*)d_in[2];
    const float* bvec  = (const float*)d_in[3];
    const float* mlp_w = (const float*)d_in[4];
    const float* mlp_b = (const float*)d_in[5];
    const float* fc_w  = (const float*)d_in[6];
    const float* fc_b  = (const float*)d_in[7];
    const float* out_w = (const float*)d_in[8];
    const float* out_b = (const float*)d_in[9];
    float* out = (float*)d_out;

    const int smem_w2 = (3072 + 12288 + 1024) * 4;   // 65536

    cudaFuncSetAttribute(w2_kernel,     cudaFuncAttributeMaxDynamicSharedMemorySize, smem_w2);
    cudaFuncSetAttribute(gx_mma_kernel, cudaFuncAttributeMaxDynamicSharedMemorySize, GXM_SMEM);

    w2_kernel<<<TT, 256, smem_w2>>>(mlp_w, mlp_b, fc_w, out_w);
    bias_final_kernel<<<1, 32>>>(fc_b, out_w, out_b);
    wsplit_kernel<<<GG, 128>>>(w_i);
    gx_mma_kernel<<<(BB * TT / 64) * 3, 256, GXM_SMEM>>>(x, bvec);
    rec_kernel<<<BB / 8, 512>>>(w_h);
    fc_kernel<<<BB / 8, 512>>>(out);
}

// round 12
// speedup vs baseline: 1.0336x; 1.0336x over previous
#include <cuda_runtime.h>
#include <cuda_bf16.h>
#include <cstdint>

// Problem constants (fixed by the dataset)
#define BB   1024
#define TT   256
#define INDIM 128
#define HH   128
#define GG   384      // 3*H
#define HOR  24

// ---------------- scratch (device globals; no allocations allowed) ----------
__device__ float g_gx[(size_t)TT * BB * GG];        // 384 MB: x@w_i + b, [t][b][g]
__device__ float g_ys[(size_t)TT * BB * HH];        // 128 MB: hidden states, [t][b][j]
__device__ float g_W2[(size_t)TT * HH * HOR];       // 3 MB: folded weights, [t][j][p]
__device__ float g_bias_part[TT * HOR];
__device__ float g_final_bias[HOR];
__device__ __nv_bfloat16 g_whi[GG * INDIM];         // w_i^T hi, [n][k]
__device__ __nv_bfloat16 g_wlo[GG * INDIM];         // w_i^T lo, [n][k]

// ---------------- packed f32x2 helpers (bit-exact vs 2x scalar) -------------
typedef unsigned long long u64;

__device__ __forceinline__ u64 pack2(float lo, float hi) {
    u64 r; asm("mov.b64 %0, {%1, %2};" : "=l"(r) : "f"(lo), "f"(hi)); return r;
}
__device__ __forceinline__ u64 dup2(float v) {
    u64 r; asm("mov.b64 %0, {%1, %1};" : "=l"(r) : "f"(v)); return r;
}
__device__ __forceinline__ void unpack2(u64 v, float& lo, float& hi) {
    asm("mov.b64 {%0, %1}, %2;" : "=f"(lo), "=f"(hi) : "l"(v));
}
__device__ __forceinline__ void ffma2(u64& d, u64 a, u64 b) {
    asm("fma.rn.f32x2 %0, %1, %2, %0;" : "+l"(d) : "l"(a), "l"(b));
}
__device__ __forceinline__ void fadd2(u64& d, u64 a) {
    asm("add.rn.f32x2 %0, %0, %1;" : "+l"(d) : "l"(a));
}
__device__ __forceinline__ u64 shfl_xor_u64(u64 v, int m) {
    uint32_t lo = (uint32_t)v, hi = (uint32_t)(v >> 32);
    lo = __shfl_xor_sync(0xffffffffu, lo, m);
    hi = __shfl_xor_sync(0xffffffffu, hi, m);
    return ((u64)hi << 32) | (u64)lo;
}

// ---------------- mma.sync / ldmatrix helpers (sm_100 baseline ISA) ----------
__device__ __forceinline__ uint32_t smem_u32(const void* p) {
    uint32_t a;
    asm("{ .reg .u64 t; cvta.to.shared.u64 t, %1; cvt.u32.u64 %0, t; }" : "=r"(a) : "l"(p));
    return a;
}
__device__ __forceinline__ void ldsm_x4(uint32_t* r, uint32_t addr) {
    asm volatile("ldmatrix.sync.aligned.m8n8.x4.shared.b16 {%0,%1,%2,%3}, [%4];"
                 : "=r"(r[0]), "=r"(r[1]), "=r"(r[2]), "=r"(r[3]) : "r"(addr));
}
__device__ __forceinline__ void mma_bf16(float* d, const uint32_t* a,
                                         uint32_t b0, uint32_t b1) {
    asm volatile(
        "mma.sync.aligned.m16n8k16.row.col.f32.bf16.bf16.f32 "
        "{%0,%1,%2,%3}, {%4,%5,%6,%7}, {%8,%9}, {%0,%1,%2,%3};"
        : "+f"(d[0]), "+f"(d[1]), "+f"(d[2]), "+f"(d[3])
        : "r"(a[0]), "r"(a[1]), "r"(a[2]), "r"(a[3]), "r"(b0), "r"(b1));
}
__device__ __forceinline__ void cp_async16(uint32_t dst, const void* src) {
    asm volatile("cp.async.ca.shared.global [%0], [%1], 16;"
                 :: "r"(dst), "l"(src));
}
// swizzled byte offset for bf16 tile [row][col], 256B rows, 16B chunks
__device__ __forceinline__ uint32_t swz(int row, int c16) {
    return (uint32_t)(row * 256 + ((c16 ^ (row & 7)) << 4));
}

// ---------------- activation helpers ----------------------------------------
__device__ __forceinline__ float sigmoid_f(float x) {
    return 1.0f / (1.0f + __expf(-x));
}
__device__ __forceinline__ float tanh_f(float x) {
    float ax = fabsf(x);
    float e  = __expf(2.0f * ax);
    float r  = 1.0f - 2.0f / (e + 1.0f);
    return copysignf(r, x);
}

// ============================================================================
// Kernel 1: fold  W2_t = mlp_w @ (fc_w_t @ out_w)  and bias partial per t.
// ============================================================================
__global__ void __launch_bounds__(256) w2_kernel(
    const float* __restrict__ mlp_w,   // [128,512]
    const float* __restrict__ mlp_b,   // [512]
    const float* __restrict__ fc_w,    // [131072,128]
    const float* __restrict__ out_w)   // [128,24]
{
    extern __shared__ float sm[];
    float* ows    = sm;
    float* P      = sm + 3072;
    float* rowbuf = sm + 3072 + 12288;
    const int tid  = threadIdx.x;
    const int t    = blockIdx.x;
    const int warp = tid >> 5;
    const int lane = tid & 31;

    for (int i = tid; i < HH * HOR; i += 256) ows[i] = out_w[i];
    __syncthreads();

    const float* fcb = fc_w + (size_t)t * 512 * HH;
    for (int j = warp; j < 512; j += 8) {
        float4 v = ((const float4*)(fcb + (size_t)j * HH))[lane];
        ((float4*)(rowbuf + warp * 128))[lane] = v;
        __syncwarp();
        if (lane < HOR) {
            const float* rb = rowbuf + warp * 128;
            float acc = 0.0f;
            #pragma unroll 4
            for (int k = 0; k < 128; k++) acc = fmaf(rb[k], ows[k * HOR + lane], acc);
            P[j * HOR + lane] = acc;
        }
        __syncwarp();
    }
    __syncthreads();

    if (warp == 0 && lane < HOR) {
        float acc = 0.0f;
        for (int j = 0; j < 512; j++) acc = fmaf(mlp_b[j], P[j * HOR + lane], acc);
        g_bias_part[t * HOR + lane] = acc;
    }

    const int i  = tid & 127;
    const int p0 = (tid >> 7) * 12;
    float acc[12];
    #pragma unroll
    for (int q = 0; q < 12; q++) acc[q] = 0.0f;
    const float* mw = mlp_w + (size_t)i * 512;
    for (int j = 0; j < 512; j++) {
        float m = mw[j];
        const float* pr = P + j * HOR + p0;
        #pragma unroll
        for (int q = 0; q < 12; q++) acc[q] = fmaf(m, pr[q], acc[q]);
    }
    float* dst = g_W2 + ((size_t)t * HH + i) * HOR + p0;
    #pragma unroll
    for (int q = 0; q < 12; q++) dst[q] = acc[q];
}

// ============================================================================
// Kernel 2: final bias = sum_t bias_part + fc_b@out_w + out_b
// ============================================================================
__global__ void bias_final_kernel(const float* __restrict__ fc_b,
                                  const float* __restrict__ out_w,
                                  const float* __restrict__ out_b)
{
    int p = threadIdx.x;
    if (p >= HOR) return;
    float s = out_b[p];
    for (int t = 0; t < TT; t++) s += g_bias_part[t * HOR + p];
    for (int o = 0; o < HH; o++) s = fmaf(fc_b[o], out_w[o * HOR + p], s);
    g_final_bias[p] = s;
}

// ============================================================================
// Kernel 2b: split w_i into bf16 hi/lo, transposed to [n][k] (B operand).
// ============================================================================
__global__ void wsplit_kernel(const float* __restrict__ w_i)  // [128k][384n]
{
    int n = blockIdx.x;     // 0..383
    int k = threadIdx.x;    // 0..127
    float v = w_i[(size_t)k * GG + n];
    __nv_bfloat16 h = __float2bfloat16(v);
    float lo = v - __bfloat162float(h);
    g_whi[n * INDIM + k] = h;
    g_wlo[n * INDIM + k] = __float2bfloat16(lo);
}

// ============================================================================
// Kernel 3 (v9): gx = x @ w_i + b via mma.sync bf16 3-term split, FUSED passes.
// CTA = 128 rows x 1 gate (N=128), K=128; 8 warps 4(m)x2(n), warp m32 x n64.
// Per k-step: A_hi(2 ldsm)+B_hi(4) -> hh mma; B_lo(4) -> hl; A_lo(2) -> lh.
// 12 ldsm / 48 mma per warp-kstep (vs 18/48 unfused): -33% ldsm L1 traffic.
// B staged via cp.async (no LDG->STS roundtrip), overlapped with A convert.
// ============================================================================
#define GXM_A_HI  0
#define GXM_A_LO  32768
#define GXM_B_HI  65536
#define GXM_B_LO  98304
#define GXM_SMEM  131072

__global__ void __launch_bounds__(256, 1) gx_mma_kernel(
    const float* __restrict__ x,     // [B][T][128] == [m][128]
    const float* __restrict__ bvec)  // [384]
{
    extern __shared__ char smemc[];
    const int tid  = threadIdx.x;
    const int wid  = tid >> 5;
    const int lane = tid & 31;
    const int gate = blockIdx.x % 3;
    const int m0g  = (blockIdx.x / 3) * 128;
    uint32_t sbase = smem_u32(smemc);

    // ---- stage B via cp.async (in flight while A converts) ----
    {
        int row = tid >> 1, half = tid & 1;     // row = n index
        size_t src = (size_t)(gate * 128 + row) * INDIM + half * 64;
        const char* bh = (const char*)(g_whi + src);
        const char* bl = (const char*)(g_wlo + src);
        #pragma unroll
        for (int u = 0; u < 8; u++) {
            uint32_t o = swz(row, half * 8 + u);
            cp_async16(sbase + GXM_B_HI + o, bh + u * 16);
            cp_async16(sbase + GXM_B_LO + o, bl + u * 16);
        }
        asm volatile("cp.async.commit_group;" ::: "memory");
    }
    // ---- stage A: read x fp32, split to bf16 hi/lo, store swizzled ----
    {
        int row = tid >> 1, half = tid & 1;
        const float4* xr = (const float4*)(x + (size_t)(m0g + row) * INDIM + half * 64);
        #pragma unroll
        for (int u = 0; u < 8; u++) {
            float4 a = xr[2 * u], b = xr[2 * u + 1];
            float f[8] = {a.x, a.y, a.z, a.w, b.x, b.y, b.z, b.w};
            uint32_t hi[4], lo[4];
            #pragma unroll
            for (int p = 0; p < 4; p++) {
                __nv_bfloat162 h = __floats2bfloat162_rn(f[2*p], f[2*p+1]);
                hi[p] = *(uint32_t*)&h;
                float l0 = f[2*p]     - __bfloat162float(h.x);
                float l1 = f[2*p + 1] - __bfloat162float(h.y);
                __nv_bfloat162 l = __floats2bfloat162_rn(l0, l1);
                lo[p] = *(uint32_t*)&l;
            }
            uint32_t o = swz(row, half * 8 + u);
            *(uint4*)(smemc + GXM_A_HI + o) = make_uint4(hi[0], hi[1], hi[2], hi[3]);
            *(uint4*)(smemc + GXM_A_LO + o) = make_uint4(lo[0], lo[1], lo[2], lo[3]);
        }
    }
    asm volatile("cp.async.wait_group 0;" ::: "memory");
    __syncthreads();

    // warp tile: m-rows [m0w, m0w+32), n-cols [n0w, n0w+64)
    const int m0w = (wid & 3) * 32;
    const int n0w = (wid >> 2) * 64;
    const int lr  = lane & 15;          // ldmatrix row-within-16
    const int lc  = lane >> 4;          // ldmatrix chunk select (k8 halves)

    float acc[2][8][4];
    #pragma unroll
    for (int mi = 0; mi < 2; mi++)
        #pragma unroll
        for (int nt = 0; nt < 8; nt++)
            #pragma unroll
            for (int q = 0; q < 4; q++) acc[mi][nt][q] = 0.0f;

    #pragma unroll
    for (int s = 0; s < 8; s++) {
        const int c16 = 2 * s + lc;
        const int ra  = m0w + lr;

        // A_hi fragments (reused by hh and hl... hh and lh share B_hi; hh/hl share A_hi)
        uint32_t a0[4], a1[4];
        ldsm_x4(a0, sbase + GXM_A_HI + swz(ra, c16));
        ldsm_x4(a1, sbase + GXM_A_HI + swz(ra + 16, c16));

        // B_hi fragments
        uint32_t bh[4][4];
        #pragma unroll
        for (int q = 0; q < 4; q++)
            ldsm_x4(bh[q], sbase + GXM_B_HI + swz(n0w + q * 16 + lr, c16));

        // pass hh: A_hi x B_hi
        #pragma unroll
        for (int nt = 0; nt < 8; nt++) {
            int q = nt >> 1, sel = nt & 1;
            mma_bf16(acc[0][nt], a0, bh[q][sel], bh[q][sel + 2]);
            mma_bf16(acc[1][nt], a1, bh[q][sel], bh[q][sel + 2]);
        }

        // pass hl: A_hi x B_lo (reuse a0/a1)
        {
            uint32_t bl[4][4];
            #pragma unroll
            for (int q = 0; q < 4; q++)
                ldsm_x4(bl[q], sbase + GXM_B_LO + swz(n0w + q * 16 + lr, c16));
            #pragma unroll
            for (int nt = 0; nt < 8; nt++) {
                int q = nt >> 1, sel = nt & 1;
                mma_bf16(acc[0][nt], a0, bl[q][sel], bl[q][sel + 2]);
                mma_bf16(acc[1][nt], a1, bl[q][sel], bl[q][sel + 2]);
            }
        }

        // pass lh: A_lo x B_hi (reuse bh)
        {
            uint32_t l0[4], l1[4];
            ldsm_x4(l0, sbase + GXM_A_LO + swz(ra, c16));
            ldsm_x4(l1, sbase + GXM_A_LO + swz(ra + 16, c16));
            #pragma unroll
            for (int nt = 0; nt < 8; nt++) {
                int q = nt >> 1, sel = nt & 1;
                mma_bf16(acc[0][nt], l0, bh[q][sel], bh[q][sel + 2]);
                mma_bf16(acc[1][nt], l1, bh[q][sel], bh[q][sel + 2]);
            }
        }
    }

    // ---- epilogue: bias + store ----
    const int colq = (lane & 3) * 2;
    #pragma unroll
    for (int nt = 0; nt < 8; nt++) {
        int c = n0w + nt * 8 + colq;
        float2 bv = *(const float2*)(bvec + gate * 128 + c);
        #pragma unroll
        for (int mi = 0; mi < 2; mi++) {
            int gm0 = m0g + m0w + 16 * mi + (lane >> 2);
            #pragma unroll
            for (int h = 0; h < 2; h++) {
                int gm = gm0 + 8 * h;
                int tt = gm & 255, bb = gm >> 8;
                float2 o;
                o.x = acc[mi][nt][2 * h + 0] + bv.x;
                o.y = acc[mi][nt][2 * h + 1] + bv.y;
                *(float2*)(g_gx + ((size_t)tt * BB + bb) * GG + gate * 128 + c) = o;
            }
        }
    }
}

// ============================================================================
// Kernel 4 (v7, unchanged): recurrence. w_h in regs, deep k-split + shuffles.
// ============================================================================
__global__ void __launch_bounds__(512, 1) rec_kernel(
    const float* __restrict__ w_h)   // [128][384]
{
    __shared__ float hT[1024];    // [j][r]
    __shared__ float rhT[1024];   // [j][r]
    __shared__ float zs[1024];    // [col][r]

    const int tid = threadIdx.x;
    const int w   = tid >> 5;
    const int l   = tid & 31;
    const int b0  = blockIdx.x * 8;

    const int colA = w * 16 + 2 * (l & 7);
    const int s1   = l >> 3;
    const int rz   = 2 * s1;
    const int colB = w * 8 + 2 * (l & 3);
    const int s3   = l >> 2;
    const int jf2  = 2 * (s3 & 1) + ((s3 >> 1) & 1);
    const int rF   = 2 * jf2 + (s3 >> 2);
    const int jA   = colA - 128;

    float wzA[32], wzB[32];
    #pragma unroll
    for (int i = 0; i < 32; i++) {
        wzA[i] = __ldg(w_h + (size_t)(4 * i + s1) * GG + colA);
        wzB[i] = __ldg(w_h + (size_t)(4 * i + s1) * GG + colA + 1);
    }
    float waA[16], waB[16];
    #pragma unroll
    for (int i = 0; i < 16; i++) {
        waA[i] = __ldg(w_h + (size_t)(8 * i + s3) * GG + 256 + colB);
        waB[i] = __ldg(w_h + (size_t)(8 * i + s3) * GG + 256 + colB + 1);
    }

    for (int i = tid; i < 1024; i += 512) hT[i] = 0.0f;
    __syncthreads();

    float2 g1a, g1b;
    {
        const float* g0 = g_gx + (size_t)b0 * GG;
        g1a = *(const float2*)(g0 + (rz + 0) * GG + colA);
        g1b = *(const float2*)(g0 + (rz + 1) * GG + colA);
    }

    for (int t = 0; t < TT; t++) {
        const float* gxt = g_gx + ((size_t)t * BB + b0) * GG;
        float2 g2 = *(const float2*)(gxt + rF * GG + 256 + colB);

        u64 pA[4] = {0ULL,0ULL,0ULL,0ULL};
        u64 pB[4] = {0ULL,0ULL,0ULL,0ULL};
        #pragma unroll
        for (int i = 0; i < 32; i++) {
            const float* hp = &hT[(4 * i + s1) * 8];
            ulonglong2 h0 = *(const ulonglong2*)hp;
            ulonglong2 h1 = *(const ulonglong2*)(hp + 4);
            u64 wdA = dup2(wzA[i]);
            u64 wdB = dup2(wzB[i]);
            ffma2(pA[0], h0.x, wdA); ffma2(pA[1], h0.y, wdA);
            ffma2(pA[2], h1.x, wdA); ffma2(pA[3], h1.y, wdA);
            ffma2(pB[0], h0.x, wdB); ffma2(pB[1], h0.y, wdB);
            ffma2(pB[2], h1.x, wdB); ffma2(pB[3], h1.y, wdB);
        }
        {
            u64 tA0 = shfl_xor_u64(pA[0], 16), tA1 = shfl_xor_u64(pA[1], 16);
            u64 tA2 = shfl_xor_u64(pA[2], 16), tA3 = shfl_xor_u64(pA[3], 16);
            u64 tB0 = shfl_xor_u64(pB[0], 16), tB1 = shfl_xor_u64(pB[1], 16);
            u64 tB2 = shfl_xor_u64(pB[2], 16), tB3 = shfl_xor_u64(pB[3], 16);
            bool hiB = (s1 & 2) != 0;
            u64 kA0 = hiB ? pA[2] : pA[0], rA0 = hiB ? tA2 : tA0;
            u64 kA1 = hiB ? pA[3] : pA[1], rA1 = hiB ? tA3 : tA1;
            u64 kB0 = hiB ? pB[2] : pB[0], rB0 = hiB ? tB2 : tB0;
            u64 kB1 = hiB ? pB[3] : pB[1], rB1 = hiB ? tB3 : tB1;
            fadd2(kA0, rA0); fadd2(kA1, rA1);
            fadd2(kB0, rB0); fadd2(kB1, rB1);
            u64 uA0 = shfl_xor_u64(kA0, 8), uA1 = shfl_xor_u64(kA1, 8);
            u64 uB0 = shfl_xor_u64(kB0, 8), uB1 = shfl_xor_u64(kB1, 8);
            bool hi0 = (s1 & 1) != 0;
            u64 fA = hi0 ? kA1 : kA0, gA = hi0 ? uA1 : uA0;
            u64 fB = hi0 ? kB1 : kB0, gB = hi0 ? uB1 : uB0;
            fadd2(fA, gA); fadd2(fB, gB);

            float aA0, aA1, aB0, aB1;
            unpack2(fA, aA0, aA1);
            unpack2(fB, aB0, aB1);
            aA0 += g1a.x; aB0 += g1a.y;
            aA1 += g1b.x; aB1 += g1b.y;

            if (colA < 128) {
                float2 vA = make_float2(sigmoid_f(aA0), sigmoid_f(aA1));
                float2 vB = make_float2(sigmoid_f(aB0), sigmoid_f(aB1));
                *(float2*)&zs[(colA + 0) * 8 + rz] = vA;
                *(float2*)&zs[(colA + 1) * 8 + rz] = vB;
            } else {
                float2 hA = *(const float2*)&hT[(jA + 0) * 8 + rz];
                float2 hB = *(const float2*)&hT[(jA + 1) * 8 + rz];
                float2 oA = make_float2(sigmoid_f(aA0) * hA.x, sigmoid_f(aA1) * hA.y);
                float2 oB = make_float2(sigmoid_f(aB0) * hB.x, sigmoid_f(aB1) * hB.y);
                *(float2*)&rhT[(jA + 0) * 8 + rz] = oA;
                *(float2*)&rhT[(jA + 1) * 8 + rz] = oB;
            }
        }

        if (t + 1 < TT) {
            const float* gxn = g_gx + ((size_t)(t + 1) * BB + b0) * GG;
            g1a = *(const float2*)(gxn + (rz + 0) * GG + colA);
            g1b = *(const float2*)(gxn + (rz + 1) * GG + colA);
        }
        __syncthreads();

        u64 qA[4] = {0ULL,0ULL,0ULL,0ULL};
        u64 qB[4] = {0ULL,0ULL,0ULL,0ULL};
        #pragma unroll
        for (int i = 0; i < 16; i++) {
            const float* rp = &rhT[(8 * i + s3) * 8];
            ulonglong2 r0 = *(const ulonglong2*)rp;
            ulonglong2 r1 = *(const ulonglong2*)(rp + 4);
            u64 wdA = dup2(waA[i]);
            u64 wdB = dup2(waB[i]);
            ffma2(qA[0], r0.x, wdA); ffma2(qA[1], r0.y, wdA);
            ffma2(qA[2], r1.x, wdA); ffma2(qA[3], r1.y, wdA);
            ffma2(qB[0], r0.x, wdB); ffma2(qB[1], r0.y, wdB);
            ffma2(qB[2], r1.x, wdB); ffma2(qB[3], r1.y, wdB);
        }
        float vA, vB;
        {
            u64 tA0 = shfl_xor_u64(qA[0], 4), tA1 = shfl_xor_u64(qA[1], 4);
            u64 tA2 = shfl_xor_u64(qA[2], 4), tA3 = shfl_xor_u64(qA[3], 4);
            u64 tB0 = shfl_xor_u64(qB[0], 4), tB1 = shfl_xor_u64(qB[1], 4);
            u64 tB2 = shfl_xor_u64(qB[2], 4), tB3 = shfl_xor_u64(qB[3], 4);
            bool hiB = (s3 & 1) != 0;
            u64 kA0 = hiB ? qA[2] : qA[0], rA0 = hiB ? tA2 : tA0;
            u64 kA1 = hiB ? qA[3] : qA[1], rA1 = hiB ? tA3 : tA1;
            u64 kB0 = hiB ? qB[2] : qB[0], rB0 = hiB ? tB2 : tB0;
            u64 kB1 = hiB ? qB[3] : qB[1], rB1 = hiB ? tB3 : tB1;
            fadd2(kA0, rA0); fadd2(kA1, rA1);
            fadd2(kB0, rB0); fadd2(kB1, rB1);
            u64 uA0 = shfl_xor_u64(kA0, 8), uA1 = shfl_xor_u64(kA1, 8);
            u64 uB0 = shfl_xor_u64(kB0, 8), uB1 = shfl_xor_u64(kB1, 8);
            bool hi1 = ((s3 >> 1) & 1) != 0;
            u64 fA = hi1 ? kA1 : kA0, gA = hi1 ? uA1 : uA0;
            u64 fB = hi1 ? kB1 : kB0, gB = hi1 ? uB1 : uB0;
            fadd2(fA, gA); fadd2(fB, gB);
            float loA, hiA_, loB, hiB_;
            unpack2(fA, loA, hiA_);
            unpack2(fB, loB, hiB_);
            bool top = (s3 & 4) != 0;
            float sendA = top ? loA : hiA_;
            float sendB = top ? loB : hiB_;
            float rcvA = __shfl_xor_sync(0xffffffffu, sendA, 16);
            float rcvB = __shfl_xor_sync(0xffffffffu, sendB, 16);
            vA = (top ? hiA_ : loA) + rcvA;
            vB = (top ? hiB_ : loB) + rcvB;
        }
        {
            float z0 = zs[(colB + 0) * 8 + rF];
            float z1 = zs[(colB + 1) * 8 + rF];
            float h0 = hT[(colB + 0) * 8 + rF];
            float h1 = hT[(colB + 1) * 8 + rF];
            float hn0 = fmaf(z0, tanh_f(vA + g2.x) - h0, h0);
            float hn1 = fmaf(z1, tanh_f(vB + g2.y) - h1, h1);
            hT[(colB + 0) * 8 + rF] = hn0;
            hT[(colB + 1) * 8 + rF] = hn1;
            *(float2*)&g_ys[((size_t)t * BB + b0 + rF) * HH + colB] = make_float2(hn0, hn1);
        }
        __syncthreads();
    }
}

// ============================================================================
// Kernel 5 (unchanged): out[b,p] = sum_t sum_j ys[t,b,j]*W2[t,j,p] + bias.
// ============================================================================
__global__ void __launch_bounds__(512, 1) fc_kernel(float* __restrict__ out)
{
    __shared__ float red[8 * HOR * 4];

    const int tid = threadIdx.x;
    const int j   = tid & 127;
    const int g   = tid >> 7;
    const int b0  = blockIdx.x * 8;
    const int lane = tid & 31;
    const int jblk = (j >> 5);

    u64 acc[2][12];
    #pragma unroll
    for (int u = 0; u < 2; u++)
        #pragma unroll
        for (int q = 0; q < 12; q++) acc[u][q] = 0ULL;

    #pragma unroll 2
    for (int t = 0; t < TT; t++) {
        const float* ysp = g_ys + ((size_t)t * BB + b0 + 2 * g) * HH + j;
        float y0 = __ldg(ysp);
        float y1 = __ldg(ysp + HH);
        const ulonglong2* wp = (const ulonglong2*)(g_W2 + ((size_t)t * HH + j) * HOR);
        ulonglong2 w0 = wp[0], w1 = wp[1], w2 = wp[2],
                   w3 = wp[3], w4 = wp[4], w5 = wp[5];
        u64 wq[12] = {w0.x, w0.y, w1.x, w1.y, w2.x, w2.y,
                      w3.x, w3.y, w4.x, w4.y, w5.x, w5.y};
        u64 y0d = dup2(y0), y1d = dup2(y1);
        #pragma unroll
        for (int q = 0; q < 12; q++) {
            ffma2(acc[0][q], y0d, wq[q]);
            ffma2(acc[1][q], y1d, wq[q]);
        }
    }

    #pragma unroll
    for (int u = 0; u < 2; u++)
        #pragma unroll
        for (int q = 0; q < 12; q++) {
            fadd2(acc[u][q], shfl_xor_u64(acc[u][q], 1));
            fadd2(acc[u][q], shfl_xor_u64(acc[u][q], 2));
            fadd2(acc[u][q], shfl_xor_u64(acc[u][q], 4));
            fadd2(acc[u][q], shfl_xor_u64(acc[u][q], 8));
            fadd2(acc[u][q], shfl_xor_u64(acc[u][q], 16));
        }

    if (lane == 0) {
        #pragma unroll
        for (int u = 0; u < 2; u++) {
            int row = 2 * g + u;
            #pragma unroll
            for (int q = 0; q < 12; q++) {
                float v0, v1;
                unpack2(acc[u][q], v0, v1);
                red[(row * HOR + 2 * q + 0) * 4 + jblk] = v0;
                red[(row * HOR + 2 * q + 1) * 4 + jblk] = v1;
            }
        }
    }
    __syncthreads();

    if (tid < 8 * HOR) {
        int row = tid / HOR;
        int p   = tid - row * HOR;
        const float* pp = red + (row * HOR + p) * 4;
        float s = ((pp[0] + pp[1]) + pp[2]) + pp[3];
        out[(size_t)(b0 + row) * HOR + p] = s + g_final_bias[p];
    }
}

// ============================================================================
// launch
// ============================================================================
extern "C" void kernel_launch(void* const* d_in, const int* in_sizes, int n_in,
                              void* d_out, int out_size)
{
    const float* x     = (const float*)d_in[0];
    const float* w_i   = (const float*)d_in[1];
    const float* w_h   = (const float*)d_in[2];
    const float* bvec  = (const float*)d_in[3];
    const float* mlp_w = (const float*)d_in[4];
    const float* mlp_b = (const float*)d_in[5];
    const float* fc_w  = (const float*)d_in[6];
    const float* fc_b  = (const float*)d_in[7];
    const float* out_w = (const float*)d_in[8];
    const float* out_b = (const float*)d_in[9];
    float* out = (float*)d_out;

    const int smem_w2 = (3072 + 12288 + 1024) * 4;   // 65536

    cudaFuncSetAttribute(w2_kernel,     cudaFuncAttributeMaxDynamicSharedMemorySize, smem_w2);
    cudaFuncSetAttribute(gx_mma_kernel, cudaFuncAttributeMaxDynamicSharedMemorySize, GXM_SMEM);

    w2_kernel<<<TT, 256, smem_w2>>>(mlp_w, mlp_b, fc_w, out_w);
    bias_final_kernel<<<1, 32>>>(fc_b, out_w, out_b);
    wsplit_kernel<<<GG, 128>>>(w_i);
    gx_mma_kernel<<<(BB * TT / 128) * 3, 256, GXM_SMEM>>>(x, bvec);
    rec_kernel<<<BB / 8, 512>>>(w_h);
    fc_kernel<<<BB / 8, 512>>>(out);
}

// round 13
// speedup vs baseline: 1.1131x; 1.0770x over previous
#include <cuda_runtime.h>
#include <cuda_bf16.h>
#include <cstdint>

// Problem constants (fixed by the dataset)
#define BB   1024
#define TT   256
#define INDIM 128
#define HH   128
#define GG   384      // 3*H
#define HOR  24

// ---------------- scratch (device globals; no allocations allowed) ----------
__device__ float g_gx[(size_t)TT * BB * GG];        // 384 MB: x@w_i + b, [t][b][g]
__device__ float g_ys[(size_t)TT * BB * HH];        // 128 MB: hidden states, [t][b][j]
__device__ float g_W2[(size_t)TT * HH * HOR];       // 3 MB: folded weights, [t][j][p]
__device__ float g_bias_part[TT * HOR];
__device__ float g_final_bias[HOR];
__device__ __nv_bfloat16 g_whi[GG * INDIM];         // w_i^T hi, [n][k]
__device__ __nv_bfloat16 g_wlo[GG * INDIM];         // w_i^T lo, [n][k]

// ---------------- packed f32x2 helpers (bit-exact vs 2x scalar) -------------
typedef unsigned long long u64;

__device__ __forceinline__ u64 pack2(float lo, float hi) {
    u64 r; asm("mov.b64 %0, {%1, %2};" : "=l"(r) : "f"(lo), "f"(hi)); return r;
}
__device__ __forceinline__ u64 dup2(float v) {
    u64 r; asm("mov.b64 %0, {%1, %1};" : "=l"(r) : "f"(v)); return r;
}
__device__ __forceinline__ void unpack2(u64 v, float& lo, float& hi) {
    asm("mov.b64 {%0, %1}, %2;" : "=f"(lo), "=f"(hi) : "l"(v));
}
__device__ __forceinline__ void ffma2(u64& d, u64 a, u64 b) {
    asm("fma.rn.f32x2 %0, %1, %2, %0;" : "+l"(d) : "l"(a), "l"(b));
}
__device__ __forceinline__ void fadd2(u64& d, u64 a) {
    asm("add.rn.f32x2 %0, %0, %1;" : "+l"(d) : "l"(a));
}
__device__ __forceinline__ u64 shfl_xor_u64(u64 v, int m) {
    uint32_t lo = (uint32_t)v, hi = (uint32_t)(v >> 32);
    lo = __shfl_xor_sync(0xffffffffu, lo, m);
    hi = __shfl_xor_sync(0xffffffffu, hi, m);
    return ((u64)hi << 32) | (u64)lo;
}

// ---------------- mma.sync / ldmatrix helpers (sm_100 baseline ISA) ----------
__device__ __forceinline__ uint32_t smem_u32(const void* p) {
    uint32_t a;
    asm("{ .reg .u64 t; cvta.to.shared.u64 t, %1; cvt.u32.u64 %0, t; }" : "=r"(a) : "l"(p));
    return a;
}
__device__ __forceinline__ void ldsm_x4(uint32_t* r, uint32_t addr) {
    asm volatile("ldmatrix.sync.aligned.m8n8.x4.shared.b16 {%0,%1,%2,%3}, [%4];"
                 : "=r"(r[0]), "=r"(r[1]), "=r"(r[2]), "=r"(r[3]) : "r"(addr));
}
__device__ __forceinline__ void mma_bf16(float* d, const uint32_t* a,
                                         uint32_t b0, uint32_t b1) {
    asm volatile(
        "mma.sync.aligned.m16n8k16.row.col.f32.bf16.bf16.f32 "
        "{%0,%1,%2,%3}, {%4,%5,%6,%7}, {%8,%9}, {%0,%1,%2,%3};"
        : "+f"(d[0]), "+f"(d[1]), "+f"(d[2]), "+f"(d[3])
        : "r"(a[0]), "r"(a[1]), "r"(a[2]), "r"(a[3]), "r"(b0), "r"(b1));
}
__device__ __forceinline__ void cp_async16(uint32_t dst, const void* src) {
    asm volatile("cp.async.ca.shared.global [%0], [%1], 16;"
                 :: "r"(dst), "l"(src));
}
// swizzled byte offset for bf16 tile [row][col64], 128B rows, 16B chunks (c16 0..7)
__device__ __forceinline__ uint32_t swz128(int row, int c16) {
    return (uint32_t)(row * 128 + ((c16 ^ (row & 7)) << 4));
}

// ---------------- activation helpers ----------------------------------------
__device__ __forceinline__ float sigmoid_f(float x) {
    return 1.0f / (1.0f + __expf(-x));
}
__device__ __forceinline__ float tanh_f(float x) {
    float ax = fabsf(x);
    float e  = __expf(2.0f * ax);
    float r  = 1.0f - 2.0f / (e + 1.0f);
    return copysignf(r, x);
}

// ============================================================================
// Kernel 1: fold  W2_t = mlp_w @ (fc_w_t @ out_w)  and bias partial per t.
// P-loop now uses 4 independent partials (breaks the 128-FMA serial chain).
// ============================================================================
__global__ void __launch_bounds__(256) w2_kernel(
    const float* __restrict__ mlp_w,   // [128,512]
    const float* __restrict__ mlp_b,   // [512]
    const float* __restrict__ fc_w,    // [131072,128]
    const float* __restrict__ out_w)   // [128,24]
{
    extern __shared__ float sm[];
    float* ows    = sm;
    float* P      = sm + 3072;
    float* rowbuf = sm + 3072 + 12288;
    const int tid  = threadIdx.x;
    const int t    = blockIdx.x;
    const int warp = tid >> 5;
    const int lane = tid & 31;

    for (int i = tid; i < HH * HOR; i += 256) ows[i] = out_w[i];
    __syncthreads();

    const float* fcb = fc_w + (size_t)t * 512 * HH;
    for (int j = warp; j < 512; j += 8) {
        float4 v = ((const float4*)(fcb + (size_t)j * HH))[lane];
        ((float4*)(rowbuf + warp * 128))[lane] = v;
        __syncwarp();
        if (lane < HOR) {
            const float* rb = rowbuf + warp * 128;
            float a0 = 0.0f, a1 = 0.0f, a2 = 0.0f, a3 = 0.0f;
            #pragma unroll 8
            for (int k = 0; k < 32; k++) {
                a0 = fmaf(rb[k],      ows[(k)      * HOR + lane], a0);
                a1 = fmaf(rb[k + 32], ows[(k + 32) * HOR + lane], a1);
                a2 = fmaf(rb[k + 64], ows[(k + 64) * HOR + lane], a2);
                a3 = fmaf(rb[k + 96], ows[(k + 96) * HOR + lane], a3);
            }
            P[j * HOR + lane] = ((a0 + a1) + a2) + a3;
        }
        __syncwarp();
    }
    __syncthreads();

    if (warp == 0 && lane < HOR) {
        float acc = 0.0f;
        for (int j = 0; j < 512; j++) acc = fmaf(mlp_b[j], P[j * HOR + lane], acc);
        g_bias_part[t * HOR + lane] = acc;
    }

    const int i  = tid & 127;
    const int p0 = (tid >> 7) * 12;
    float acc[12];
    #pragma unroll
    for (int q = 0; q < 12; q++) acc[q] = 0.0f;
    const float* mw = mlp_w + (size_t)i * 512;
    for (int j = 0; j < 512; j++) {
        float m = mw[j];
        const float* pr = P + j * HOR + p0;
        #pragma unroll
        for (int q = 0; q < 12; q++) acc[q] = fmaf(m, pr[q], acc[q]);
    }
    float* dst = g_W2 + ((size_t)t * HH + i) * HOR + p0;
    #pragma unroll
    for (int q = 0; q < 12; q++) dst[q] = acc[q];
}

// ============================================================================
// Kernel 2: final bias = sum_t bias_part + fc_b@out_w + out_b
// ============================================================================
__global__ void bias_final_kernel(const float* __restrict__ fc_b,
                                  const float* __restrict__ out_w,
                                  const float* __restrict__ out_b)
{
    int p = threadIdx.x;
    if (p >= HOR) return;
    float s = out_b[p];
    for (int t = 0; t < TT; t++) s += g_bias_part[t * HOR + p];
    for (int o = 0; o < HH; o++) s = fmaf(fc_b[o], out_w[o * HOR + p], s);
    g_final_bias[p] = s;
}

// ============================================================================
// Kernel 2b: split w_i into bf16 hi/lo, transposed to [n][k] (B operand).
// ============================================================================
__global__ void wsplit_kernel(const float* __restrict__ w_i)  // [128k][384n]
{
    int n = blockIdx.x;     // 0..383
    int k = threadIdx.x;    // 0..127
    float v = w_i[(size_t)k * GG + n];
    __nv_bfloat16 h = __float2bfloat16(v);
    float lo = v - __bfloat162float(h);
    g_whi[n * INDIM + k] = h;
    g_wlo[n * INDIM + k] = __float2bfloat16(lo);
}

// ============================================================================
// Kernel 3 (v10): gx = x @ w_i + b via fused 3-term mma.sync, K-SPLIT staging.
// CTA = 128 rows x 1 gate (N=128); K processed in 2 phases of 64 cols.
// Per phase only 64 k-cols of A_hi/A_lo/B_hi/B_lo resident -> 64KB smem
// -> 2 CTAs/SM (cross-CTA overlap hides the stage->mma serial chain).
// Accumulators carry across phases. Same ldsm/mma counts as v9.
// ============================================================================
#define GXK_A_HI  0
#define GXK_A_LO  16384
#define GXK_B_HI  32768
#define GXK_B_LO  49152
#define GXK_SMEM  65536

__global__ void __launch_bounds__(256, 2) gx_mma_kernel(
    const float* __restrict__ x,     // [B][T][128] == [m][128]
    const float* __restrict__ bvec)  // [384]
{
    extern __shared__ char smemc[];
    const int tid  = threadIdx.x;
    const int wid  = tid >> 5;
    const int lane = tid & 31;
    const int gate = blockIdx.x % 3;
    const int m0g  = (blockIdx.x / 3) * 128;
    uint32_t sbase = smem_u32(smemc);

    // warp tile: m-rows [m0w, m0w+32), n-cols [n0w, n0w+64)
    const int m0w = (wid & 3) * 32;
    const int n0w = (wid >> 2) * 64;
    const int lr  = lane & 15;
    const int lc  = lane >> 4;

    float acc[2][8][4];
    #pragma unroll
    for (int mi = 0; mi < 2; mi++)
        #pragma unroll
        for (int nt = 0; nt < 8; nt++)
            #pragma unroll
            for (int q = 0; q < 4; q++) acc[mi][nt][q] = 0.0f;

    const int srow = tid >> 1;          // staging row 0..127
    const int shalf = tid & 1;          // staging col half (32 cols)

    #pragma unroll 1
    for (int ph = 0; ph < 2; ph++) {
        // ---- stage B (k-cols [ph*64, ph*64+64)) via cp.async ----
        {
            size_t src = (size_t)(gate * 128 + srow) * INDIM + ph * 64 + shalf * 32;
            const char* bh = (const char*)(g_whi + src);
            const char* bl = (const char*)(g_wlo + src);
            #pragma unroll
            for (int u = 0; u < 4; u++) {
                uint32_t o = swz128(srow, shalf * 4 + u);
                cp_async16(sbase + GXK_B_HI + o, bh + u * 16);
                cp_async16(sbase + GXK_B_LO + o, bl + u * 16);
            }
            asm volatile("cp.async.commit_group;" ::: "memory");
        }
        // ---- stage A: read x fp32 (64 cols), split bf16 hi/lo, swizzled ----
        {
            const float4* xr = (const float4*)(x + (size_t)(m0g + srow) * INDIM
                                               + ph * 64 + shalf * 32);
            #pragma unroll
            for (int u = 0; u < 4; u++) {
                float4 a = xr[2 * u], b = xr[2 * u + 1];
                float f[8] = {a.x, a.y, a.z, a.w, b.x, b.y, b.z, b.w};
                uint32_t hi[4], lo[4];
                #pragma unroll
                for (int p = 0; p < 4; p++) {
                    __nv_bfloat162 h = __floats2bfloat162_rn(f[2*p], f[2*p+1]);
                    hi[p] = *(uint32_t*)&h;
                    float l0 = f[2*p]     - __bfloat162float(h.x);
                    float l1 = f[2*p + 1] - __bfloat162float(h.y);
                    __nv_bfloat162 l = __floats2bfloat162_rn(l0, l1);
                    lo[p] = *(uint32_t*)&l;
                }
                uint32_t o = swz128(srow, shalf * 4 + u);
                *(uint4*)(smemc + GXK_A_HI + o) = make_uint4(hi[0], hi[1], hi[2], hi[3]);
                *(uint4*)(smemc + GXK_A_LO + o) = make_uint4(lo[0], lo[1], lo[2], lo[3]);
            }
        }
        asm volatile("cp.async.wait_group 0;" ::: "memory");
        __syncthreads();

        // ---- fused 3-pass MMA over this k-half (4 k16-steps) ----
        #pragma unroll
        for (int s = 0; s < 4; s++) {
            const int c16 = 2 * s + lc;
            const int ra  = m0w + lr;

            uint32_t a0[4], a1[4];
            ldsm_x4(a0, sbase + GXK_A_HI + swz128(ra, c16));
            ldsm_x4(a1, sbase + GXK_A_HI + swz128(ra + 16, c16));

            uint32_t bh[4][4];
            #pragma unroll
            for (int q = 0; q < 4; q++)
                ldsm_x4(bh[q], sbase + GXK_B_HI + swz128(n0w + q * 16 + lr, c16));

            #pragma unroll
            for (int nt = 0; nt < 8; nt++) {
                int q = nt >> 1, sel = nt & 1;
                mma_bf16(acc[0][nt], a0, bh[q][sel], bh[q][sel + 2]);
                mma_bf16(acc[1][nt], a1, bh[q][sel], bh[q][sel + 2]);
            }
            {
                uint32_t bl[4][4];
                #pragma unroll
                for (int q = 0; q < 4; q++)
                    ldsm_x4(bl[q], sbase + GXK_B_LO + swz128(n0w + q * 16 + lr, c16));
                #pragma unroll
                for (int nt = 0; nt < 8; nt++) {
                    int q = nt >> 1, sel = nt & 1;
                    mma_bf16(acc[0][nt], a0, bl[q][sel], bl[q][sel + 2]);
                    mma_bf16(acc[1][nt], a1, bl[q][sel], bl[q][sel + 2]);
                }
            }
            {
                uint32_t l0[4], l1[4];
                ldsm_x4(l0, sbase + GXK_A_LO + swz128(ra, c16));
                ldsm_x4(l1, sbase + GXK_A_LO + swz128(ra + 16, c16));
                #pragma unroll
                for (int nt = 0; nt < 8; nt++) {
                    int q = nt >> 1, sel = nt & 1;
                    mma_bf16(acc[0][nt], l0, bh[q][sel], bh[q][sel + 2]);
                    mma_bf16(acc[1][nt], l1, bh[q][sel], bh[q][sel + 2]);
                }
            }
        }
        if (ph == 0) __syncthreads();   // buffers reused by phase 1 staging
    }

    // ---- epilogue: bias + store ----
    const int colq = (lane & 3) * 2;
    #pragma unroll
    for (int nt = 0; nt < 8; nt++) {
        int c = n0w + nt * 8 + colq;
        float2 bv = *(const float2*)(bvec + gate * 128 + c);
        #pragma unroll
        for (int mi = 0; mi < 2; mi++) {
            int gm0 = m0g + m0w + 16 * mi + (lane >> 2);
            #pragma unroll
            for (int h = 0; h < 2; h++) {
                int gm = gm0 + 8 * h;
                int tt = gm & 255, bb = gm >> 8;
                float2 o;
                o.x = acc[mi][nt][2 * h + 0] + bv.x;
                o.y = acc[mi][nt][2 * h + 1] + bv.y;
                *(float2*)(g_gx + ((size_t)tt * BB + bb) * GG + gate * 128 + c) = o;
            }
        }
    }
}

// ============================================================================
// Kernel 4 (v7, unchanged): recurrence. w_h in regs, deep k-split + shuffles.
// ============================================================================
__global__ void __launch_bounds__(512, 1) rec_kernel(
    const float* __restrict__ w_h)   // [128][384]
{
    __shared__ float hT[1024];    // [j][r]
    __shared__ float rhT[1024];   // [j][r]
    __shared__ float zs[1024];    // [col][r]

    const int tid = threadIdx.x;
    const int w   = tid >> 5;
    const int l   = tid & 31;
    const int b0  = blockIdx.x * 8;

    const int colA = w * 16 + 2 * (l & 7);
    const int s1   = l >> 3;
    const int rz   = 2 * s1;
    const int colB = w * 8 + 2 * (l & 3);
    const int s3   = l >> 2;
    const int jf2  = 2 * (s3 & 1) + ((s3 >> 1) & 1);
    const int rF   = 2 * jf2 + (s3 >> 2);
    const int jA   = colA - 128;

    float wzA[32], wzB[32];
    #pragma unroll
    for (int i = 0; i < 32; i++) {
        wzA[i] = __ldg(w_h + (size_t)(4 * i + s1) * GG + colA);
        wzB[i] = __ldg(w_h + (size_t)(4 * i + s1) * GG + colA + 1);
    }
    float waA[16], waB[16];
    #pragma unroll
    for (int i = 0; i < 16; i++) {
        waA[i] = __ldg(w_h + (size_t)(8 * i + s3) * GG + 256 + colB);
        waB[i] = __ldg(w_h + (size_t)(8 * i + s3) * GG + 256 + colB + 1);
    }

    for (int i = tid; i < 1024; i += 512) hT[i] = 0.0f;
    __syncthreads();

    float2 g1a, g1b;
    {
        const float* g0 = g_gx + (size_t)b0 * GG;
        g1a = *(const float2*)(g0 + (rz + 0) * GG + colA);
        g1b = *(const float2*)(g0 + (rz + 1) * GG + colA);
    }

    for (int t = 0; t < TT; t++) {
        const float* gxt = g_gx + ((size_t)t * BB + b0) * GG;
        float2 g2 = *(const float2*)(gxt + rF * GG + 256 + colB);

        u64 pA[4] = {0ULL,0ULL,0ULL,0ULL};
        u64 pB[4] = {0ULL,0ULL,0ULL,0ULL};
        #pragma unroll
        for (int i = 0; i < 32; i++) {
            const float* hp = &hT[(4 * i + s1) * 8];
            ulonglong2 h0 = *(const ulonglong2*)hp;
            ulonglong2 h1 = *(const ulonglong2*)(hp + 4);
            u64 wdA = dup2(wzA[i]);
            u64 wdB = dup2(wzB[i]);
            ffma2(pA[0], h0.x, wdA); ffma2(pA[1], h0.y, wdA);
            ffma2(pA[2], h1.x, wdA); ffma2(pA[3], h1.y, wdA);
            ffma2(pB[0], h0.x, wdB); ffma2(pB[1], h0.y, wdB);
            ffma2(pB[2], h1.x, wdB); ffma2(pB[3], h1.y, wdB);
        }
        {
            u64 tA0 = shfl_xor_u64(pA[0], 16), tA1 = shfl_xor_u64(pA[1], 16);
            u64 tA2 = shfl_xor_u64(pA[2], 16), tA3 = shfl_xor_u64(pA[3], 16);
            u64 tB0 = shfl_xor_u64(pB[0], 16), tB1 = shfl_xor_u64(pB[1], 16);
            u64 tB2 = shfl_xor_u64(pB[2], 16), tB3 = shfl_xor_u64(pB[3], 16);
            bool hiB = (s1 & 2) != 0;
            u64 kA0 = hiB ? pA[2] : pA[0], rA0 = hiB ? tA2 : tA0;
            u64 kA1 = hiB ? pA[3] : pA[1], rA1 = hiB ? tA3 : tA1;
            u64 kB0 = hiB ? pB[2] : pB[0], rB0 = hiB ? tB2 : tB0;
            u64 kB1 = hiB ? pB[3] : pB[1], rB1 = hiB ? tB3 : tB1;
            fadd2(kA0, rA0); fadd2(kA1, rA1);
            fadd2(kB0, rB0); fadd2(kB1, rB1);
            u64 uA0 = shfl_xor_u64(kA0, 8), uA1 = shfl_xor_u64(kA1, 8);
            u64 uB0 = shfl_xor_u64(kB0, 8), uB1 = shfl_xor_u64(kB1, 8);
            bool hi0 = (s1 & 1) != 0;
            u64 fA = hi0 ? kA1 : kA0, gA = hi0 ? uA1 : uA0;
            u64 fB = hi0 ? kB1 : kB0, gB = hi0 ? uB1 : uB0;
            fadd2(fA, gA); fadd2(fB, gB);

            float aA0, aA1, aB0, aB1;
            unpack2(fA, aA0, aA1);
            unpack2(fB, aB0, aB1);
            aA0 += g1a.x; aB0 += g1a.y;
            aA1 += g1b.x; aB1 += g1b.y;

            if (colA < 128) {
                float2 vA = make_float2(sigmoid_f(aA0), sigmoid_f(aA1));
                float2 vB = make_float2(sigmoid_f(aB0), sigmoid_f(aB1));
                *(float2*)&zs[(colA + 0) * 8 + rz] = vA;
                *(float2*)&zs[(colA + 1) * 8 + rz] = vB;
            } else {
                float2 hA = *(const float2*)&hT[(jA + 0) * 8 + rz];
                float2 hB = *(const float2*)&hT[(jA + 1) * 8 + rz];
                float2 oA = make_float2(sigmoid_f(aA0) * hA.x, sigmoid_f(aA1) * hA.y);
                float2 oB = make_float2(sigmoid_f(aB0) * hB.x, sigmoid_f(aB1) * hB.y);
                *(float2*)&rhT[(jA + 0) * 8 + rz] = oA;
                *(float2*)&rhT[(jA + 1) * 8 + rz] = oB;
            }
        }

        if (t + 1 < TT) {
            const float* gxn = g_gx + ((size_t)(t + 1) * BB + b0) * GG;
            g1a = *(const float2*)(gxn + (rz + 0) * GG + colA);
            g1b = *(const float2*)(gxn + (rz + 1) * GG + colA);
        }
        __syncthreads();

        u64 qA[4] = {0ULL,0ULL,0ULL,0ULL};
        u64 qB[4] = {0ULL,0ULL,0ULL,0ULL};
        #pragma unroll
        for (int i = 0; i < 16; i++) {
            const float* rp = &rhT[(8 * i + s3) * 8];
            ulonglong2 r0 = *(const ulonglong2*)rp;
            ulonglong2 r1 = *(const ulonglong2*)(rp + 4);
            u64 wdA = dup2(waA[i]);
            u64 wdB = dup2(waB[i]);
            ffma2(qA[0], r0.x, wdA); ffma2(qA[1], r0.y, wdA);
            ffma2(qA[2], r1.x, wdA); ffma2(qA[3], r1.y, wdA);
            ffma2(qB[0], r0.x, wdB); ffma2(qB[1], r0.y, wdB);
            ffma2(qB[2], r1.x, wdB); ffma2(qB[3], r1.y, wdB);
        }
        float vA, vB;
        {
            u64 tA0 = shfl_xor_u64(qA[0], 4), tA1 = shfl_xor_u64(qA[1], 4);
            u64 tA2 = shfl_xor_u64(qA[2], 4), tA3 = shfl_xor_u64(qA[3], 4);
            u64 tB0 = shfl_xor_u64(qB[0], 4), tB1 = shfl_xor_u64(qB[1], 4);
            u64 tB2 = shfl_xor_u64(qB[2], 4), tB3 = shfl_xor_u64(qB[3], 4);
            bool hiB = (s3 & 1) != 0;
            u64 kA0 = hiB ? qA[2] : qA[0], rA0 = hiB ? tA2 : tA0;
            u64 kA1 = hiB ? qA[3] : qA[1], rA1 = hiB ? tA3 : tA1;
            u64 kB0 = hiB ? qB[2] : qB[0], rB0 = hiB ? tB2 : tB0;
            u64 kB1 = hiB ? qB[3] : qB[1], rB1 = hiB ? tB3 : tB1;
            fadd2(kA0, rA0); fadd2(kA1, rA1);
            fadd2(kB0, rB0); fadd2(kB1, rB1);
            u64 uA0 = shfl_xor_u64(kA0, 8), uA1 = shfl_xor_u64(kA1, 8);
            u64 uB0 = shfl_xor_u64(kB0, 8), uB1 = shfl_xor_u64(kB1, 8);
            bool hi1 = ((s3 >> 1) & 1) != 0;
            u64 fA = hi1 ? kA1 : kA0, gA = hi1 ? uA1 : uA0;
            u64 fB = hi1 ? kB1 : kB0, gB = hi1 ? uB1 : uB0;
            fadd2(fA, gA); fadd2(fB, gB);
            float loA, hiA_, loB, hiB_;
            unpack2(fA, loA, hiA_);
            unpack2(fB, loB, hiB_);
            bool top = (s3 & 4) != 0;
            float sendA = top ? loA : hiA_;
            float sendB = top ? loB : hiB_;
            float rcvA = __shfl_xor_sync(0xffffffffu, sendA, 16);
            float rcvB = __shfl_xor_sync(0xffffffffu, sendB, 16);
            vA = (top ? hiA_ : loA) + rcvA;
            vB = (top ? hiB_ : loB) + rcvB;
        }
        {
            float z0 = zs[(colB + 0) * 8 + rF];
            float z1 = zs[(colB + 1) * 8 + rF];
            float h0 = hT[(colB + 0) * 8 + rF];
            float h1 = hT[(colB + 1) * 8 + rF];
            float hn0 = fmaf(z0, tanh_f(vA + g2.x) - h0, h0);
            float hn1 = fmaf(z1, tanh_f(vB + g2.y) - h1, h1);
            hT[(colB + 0) * 8 + rF] = hn0;
            hT[(colB + 1) * 8 + rF] = hn1;
            *(float2*)&g_ys[((size_t)t * BB + b0 + rF) * HH + colB] = make_float2(hn0, hn1);
        }
        __syncthreads();
    }
}

// ============================================================================
// Kernel 5 (unchanged): out[b,p] = sum_t sum_j ys[t,b,j]*W2[t,j,p] + bias.
// ============================================================================
__global__ void __launch_bounds__(512, 1) fc_kernel(float* __restrict__ out)
{
    __shared__ float red[8 * HOR * 4];

    const int tid = threadIdx.x;
    const int j   = tid & 127;
    const int g   = tid >> 7;
    const int b0  = blockIdx.x * 8;
    const int lane = tid & 31;
    const int jblk = (j >> 5);

    u64 acc[2][12];
    #pragma unroll
    for (int u = 0; u < 2; u++)
        #pragma unroll
        for (int q = 0; q < 12; q++) acc[u][q] = 0ULL;

    #pragma unroll 2
    for (int t = 0; t < TT; t++) {
        const float* ysp = g_ys + ((size_t)t * BB + b0 + 2 * g) * HH + j;
        float y0 = __ldg(ysp);
        float y1 = __ldg(ysp + HH);
        const ulonglong2* wp = (const ulonglong2*)(g_W2 + ((size_t)t * HH + j) * HOR);
        ulonglong2 w0 = wp[0], w1 = wp[1], w2 = wp[2],
                   w3 = wp[3], w4 = wp[4], w5 = wp[5];
        u64 wq[12] = {w0.x, w0.y, w1.x, w1.y, w2.x, w2.y,
                      w3.x, w3.y, w4.x, w4.y, w5.x, w5.y};
        u64 y0d = dup2(y0), y1d = dup2(y1);
        #pragma unroll
        for (int q = 0; q < 12; q++) {
            ffma2(acc[0][q], y0d, wq[q]);
            ffma2(acc[1][q], y1d, wq[q]);
        }
    }

    #pragma unroll
    for (int u = 0; u < 2; u++)
        #pragma unroll
        for (int q = 0; q < 12; q++) {
            fadd2(acc[u][q], shfl_xor_u64(acc[u][q], 1));
            fadd2(acc[u][q], shfl_xor_u64(acc[u][q], 2));
            fadd2(acc[u][q], shfl_xor_u64(acc[u][q], 4));
            fadd2(acc[u][q], shfl_xor_u64(acc[u][q], 8));
            fadd2(acc[u][q], shfl_xor_u64(acc[u][q], 16));
        }

    if (lane == 0) {
        #pragma unroll
        for (int u = 0; u < 2; u++) {
            int row = 2 * g + u;
            #pragma unroll
            for (int q = 0; q < 12; q++) {
                float v0, v1;
                unpack2(acc[u][q], v0, v1);
                red[(row * HOR + 2 * q + 0) * 4 + jblk] = v0;
                red[(row * HOR + 2 * q + 1) * 4 + jblk] = v1;
            }
        }
    }
    __syncthreads();

    if (tid < 8 * HOR) {
        int row = tid / HOR;
        int p   = tid - row * HOR;
        const float* pp = red + (row * HOR + p) * 4;
        float s = ((pp[0] + pp[1]) + pp[2]) + pp[3];
        out[(size_t)(b0 + row) * HOR + p] = s + g_final_bias[p];
    }
}

// ============================================================================
// launch
// ============================================================================
extern "C" void kernel_launch(void* const* d_in, const int* in_sizes, int n_in,
                              void* d_out, int out_size)
{
    const float* x     = (const float*)d_in[0];
    const float* w_i   = (const float*)d_in[1];
    const float* w_h   = (const float*)d_in[2];
    const float* bvec  = (const float*)d_in[3];
    const float* mlp_w = (const float*)d_in[4];
    const float* mlp_b = (const float*)d_in[5];
    const float* fc_w  = (const float*)d_in[6];
    const float* fc_b  = (const float*)d_in[7];
    const float* out_w = (const float*)d_in[8];
    const float* out_b = (const float*)d_in[9];
    float* out = (float*)d_out;

    const int smem_w2 = (3072 + 12288 + 1024) * 4;   // 65536

    cudaFuncSetAttribute(w2_kernel,     cudaFuncAttributeMaxDynamicSharedMemorySize, smem_w2);
    cudaFuncSetAttribute(gx_mma_kernel, cudaFuncAttributeMaxDynamicSharedMemorySize, GXK_SMEM);

    w2_kernel<<<TT, 256, smem_w2>>>(mlp_w, mlp_b, fc_w, out_w);
    bias_final_kernel<<<1, 32>>>(fc_b, out_w, out_b);
    wsplit_kernel<<<GG, 128>>>(w_i);
    gx_mma_kernel<<<(BB * TT / 128) * 3, 256, GXK_SMEM>>>(x, bvec);
    rec_kernel<<<BB / 8, 512>>>(w_h);
    fc_kernel<<<BB / 8, 512>>>(out);
}

// round 14
// speedup vs baseline: 1.2071x; 1.0844x over previous
#include <cuda_runtime.h>
#include <cuda_bf16.h>
#include <cstdint>

// Problem constants (fixed by the dataset)
#define BB   1024
#define TT   256
#define INDIM 128
#define HH   128
#define GG   384      // 3*H
#define HOR  24

// ---------------- scratch (device globals; no allocations allowed) ----------
__device__ float g_gx[(size_t)TT * BB * GG];        // 384 MB: x@w_i + b, [t][b][g]
__device__ float g_ys[(size_t)TT * BB * HH];        // 128 MB: hidden states, [t][b][j]
__device__ float g_W2[(size_t)TT * HH * HOR];       // 3 MB: folded weights, [t][j][p]
__device__ float g_bias_part[TT * HOR];
__device__ float g_final_bias[HOR];
__device__ __nv_bfloat16 g_whi[GG * INDIM];         // w_i^T hi, [n][k]
__device__ __nv_bfloat16 g_wlo[GG * INDIM];         // w_i^T lo, [n][k]
__device__ __nv_bfloat16 g_whh_hi[GG * HH];         // w_h^T hi, [n][k]
__device__ __nv_bfloat16 g_whh_lo[GG * HH];         // w_h^T lo, [n][k]

// ---------------- packed f32x2 helpers --------------------------------------
typedef unsigned long long u64;

__device__ __forceinline__ u64 dup2(float v) {
    u64 r; asm("mov.b64 %0, {%1, %1};" : "=l"(r) : "f"(v)); return r;
}
__device__ __forceinline__ void unpack2(u64 v, float& lo, float& hi) {
    asm("mov.b64 {%0, %1}, %2;" : "=f"(lo), "=f"(hi) : "l"(v));
}
__device__ __forceinline__ void ffma2(u64& d, u64 a, u64 b) {
    asm("fma.rn.f32x2 %0, %1, %2, %0;" : "+l"(d) : "l"(a), "l"(b));
}
__device__ __forceinline__ void fadd2(u64& d, u64 a) {
    asm("add.rn.f32x2 %0, %0, %1;" : "+l"(d) : "l"(a));
}
__device__ __forceinline__ u64 shfl_xor_u64(u64 v, int m) {
    uint32_t lo = (uint32_t)v, hi = (uint32_t)(v >> 32);
    lo = __shfl_xor_sync(0xffffffffu, lo, m);
    hi = __shfl_xor_sync(0xffffffffu, hi, m);
    return ((u64)hi << 32) | (u64)lo;
}

// ---------------- mma.sync / ldmatrix helpers (sm_100 baseline ISA) ----------
__device__ __forceinline__ uint32_t smem_u32(const void* p) {
    uint32_t a;
    asm("{ .reg .u64 t; cvta.to.shared.u64 t, %1; cvt.u32.u64 %0, t; }" : "=r"(a) : "l"(p));
    return a;
}
__device__ __forceinline__ void ldsm_x4(uint32_t* r, uint32_t addr) {
    asm volatile("ldmatrix.sync.aligned.m8n8.x4.shared.b16 {%0,%1,%2,%3}, [%4];"
                 : "=r"(r[0]), "=r"(r[1]), "=r"(r[2]), "=r"(r[3]) : "r"(addr));
}
__device__ __forceinline__ void mma_bf16(float* d, const uint32_t* a,
                                         uint32_t b0, uint32_t b1) {
    asm volatile(
        "mma.sync.aligned.m16n8k16.row.col.f32.bf16.bf16.f32 "
        "{%0,%1,%2,%3}, {%4,%5,%6,%7}, {%8,%9}, {%0,%1,%2,%3};"
        : "+f"(d[0]), "+f"(d[1]), "+f"(d[2]), "+f"(d[3])
        : "r"(a[0]), "r"(a[1]), "r"(a[2]), "r"(a[3]), "r"(b0), "r"(b1));
}
__device__ __forceinline__ void cp_async16(uint32_t dst, const void* src) {
    asm volatile("cp.async.ca.shared.global [%0], [%1], 16;"
                 :: "r"(dst), "l"(src));
}
// swizzled byte offset, 256B rows (128 bf16), 16B chunks c16 in 0..15 (verified R10)
__device__ __forceinline__ uint32_t swz(int row, int c16) {
    return (uint32_t)(row * 256 + ((c16 ^ (row & 7)) << 4));
}
// swizzled byte offset, 128B rows (64 bf16), chunks 0..7 (verified R13)
__device__ __forceinline__ uint32_t swz128(int row, int c16) {
    return (uint32_t)(row * 128 + ((c16 ^ (row & 7)) << 4));
}

// ---------------- activation helpers ----------------------------------------
__device__ __forceinline__ float sigmoid_f(float x) {
    return 1.0f / (1.0f + __expf(-x));
}
__device__ __forceinline__ float tanh_f(float x) {
    float ax = fabsf(x);
    float e  = __expf(2.0f * ax);
    float r  = 1.0f - 2.0f / (e + 1.0f);
    return copysignf(r, x);
}

// bf16 hi/lo split of a value pair, stored swizzled (256B-row tile layout).
__device__ __forceinline__ void bsplit_store(char* smemc, int hiOff, int loOff,
                                             int row, int col, float v0, float v1) {
    __nv_bfloat162 h = __floats2bfloat162_rn(v0, v1);
    float l0 = v0 - __bfloat162float(h.x);
    float l1 = v1 - __bfloat162float(h.y);
    __nv_bfloat162 l = __floats2bfloat162_rn(l0, l1);
    int byte = 2 * col;   // col even -> 4B aligned
    uint32_t adr = (uint32_t)(row * 256 + ((((byte >> 4) ^ (row & 7)) << 4) | (byte & 15)));
    *(uint32_t*)(smemc + hiOff + adr) = *(uint32_t*)&h;
    *(uint32_t*)(smemc + loOff + adr) = *(uint32_t*)&l;
}

// ============================================================================
// Kernel 1: fold  W2_t = mlp_w @ (fc_w_t @ out_w)  and bias partial per t.
// ============================================================================
__global__ void __launch_bounds__(256) w2_kernel(
    const float* __restrict__ mlp_w,   // [128,512]
    const float* __restrict__ mlp_b,   // [512]
    const float* __restrict__ fc_w,    // [131072,128]
    const float* __restrict__ out_w)   // [128,24]
{
    extern __shared__ float sm[];
    float* ows    = sm;
    float* P      = sm + 3072;
    float* rowbuf = sm + 3072 + 12288;
    const int tid  = threadIdx.x;
    const int t    = blockIdx.x;
    const int warp = tid >> 5;
    const int lane = tid & 31;

    for (int i = tid; i < HH * HOR; i += 256) ows[i] = out_w[i];
    __syncthreads();

    const float* fcb = fc_w + (size_t)t * 512 * HH;
    for (int j = warp; j < 512; j += 8) {
        float4 v = ((const float4*)(fcb + (size_t)j * HH))[lane];
        ((float4*)(rowbuf + warp * 128))[lane] = v;
        __syncwarp();
        if (lane < HOR) {
            const float* rb = rowbuf + warp * 128;
            float a0 = 0.0f, a1 = 0.0f, a2 = 0.0f, a3 = 0.0f;
            #pragma unroll 8
            for (int k = 0; k < 32; k++) {
                a0 = fmaf(rb[k],      ows[(k)      * HOR + lane], a0);
                a1 = fmaf(rb[k + 32], ows[(k + 32) * HOR + lane], a1);
                a2 = fmaf(rb[k + 64], ows[(k + 64) * HOR + lane], a2);
                a3 = fmaf(rb[k + 96], ows[(k + 96) * HOR + lane], a3);
            }
            P[j * HOR + lane] = ((a0 + a1) + a2) + a3;
        }
        __syncwarp();
    }
    __syncthreads();

    if (warp == 0 && lane < HOR) {
        float acc = 0.0f;
        for (int j = 0; j < 512; j++) acc = fmaf(mlp_b[j], P[j * HOR + lane], acc);
        g_bias_part[t * HOR + lane] = acc;
    }

    const int i  = tid & 127;
    const int p0 = (tid >> 7) * 12;
    float acc[12];
    #pragma unroll
    for (int q = 0; q < 12; q++) acc[q] = 0.0f;
    const float* mw = mlp_w + (size_t)i * 512;
    for (int j = 0; j < 512; j++) {
        float m = mw[j];
        const float* pr = P + j * HOR + p0;
        #pragma unroll
        for (int q = 0; q < 12; q++) acc[q] = fmaf(m, pr[q], acc[q]);
    }
    float* dst = g_W2 + ((size_t)t * HH + i) * HOR + p0;
    #pragma unroll
    for (int q = 0; q < 12; q++) dst[q] = acc[q];
}

// ============================================================================
// Kernel 2: final bias = sum_t bias_part + fc_b@out_w + out_b
// ============================================================================
__global__ void bias_final_kernel(const float* __restrict__ fc_b,
                                  const float* __restrict__ out_w,
                                  const float* __restrict__ out_b)
{
    int p = threadIdx.x;
    if (p >= HOR) return;
    float s = out_b[p];
    for (int t = 0; t < TT; t++) s += g_bias_part[t * HOR + p];
    for (int o = 0; o < HH; o++) s = fmaf(fc_b[o], out_w[o * HOR + p], s);
    g_final_bias[p] = s;
}

// ============================================================================
// Kernel 2b/2c: split w_i and w_h into bf16 hi/lo, transposed to [n][k].
// ============================================================================
__global__ void wsplit_kernel(const float* __restrict__ w_i)  // [128k][384n]
{
    int n = blockIdx.x;
    int k = threadIdx.x;
    float v = w_i[(size_t)k * GG + n];
    __nv_bfloat16 h = __float2bfloat16(v);
    g_whi[n * INDIM + k] = h;
    g_wlo[n * INDIM + k] = __float2bfloat16(v - __bfloat162float(h));
}
__global__ void whhsplit_kernel(const float* __restrict__ w_h)  // [128k][384n]
{
    int n = blockIdx.x;
    int k = threadIdx.x;
    float v = w_h[(size_t)k * GG + n];
    __nv_bfloat16 h = __float2bfloat16(v);
    g_whh_hi[n * HH + k] = h;
    g_whh_lo[n * HH + k] = __float2bfloat16(v - __bfloat162float(h));
}

// ============================================================================
// Kernel 3 (v10, unchanged): gx via fused 3-term mma.sync, K-split staging.
// ============================================================================
#define GXK_A_HI  0
#define GXK_A_LO  16384
#define GXK_B_HI  32768
#define GXK_B_LO  49152
#define GXK_SMEM  65536

__global__ void __launch_bounds__(256, 2) gx_mma_kernel(
    const float* __restrict__ x,     // [B][T][128] == [m][128]
    const float* __restrict__ bvec)  // [384]
{
    extern __shared__ char smemc[];
    const int tid  = threadIdx.x;
    const int wid  = tid >> 5;
    const int lane = tid & 31;
    const int gate = blockIdx.x % 3;
    const int m0g  = (blockIdx.x / 3) * 128;
    uint32_t sbase = smem_u32(smemc);

    const int m0w = (wid & 3) * 32;
    const int n0w = (wid >> 2) * 64;
    const int lr  = lane & 15;
    const int lc  = lane >> 4;

    float acc[2][8][4];
    #pragma unroll
    for (int mi = 0; mi < 2; mi++)
        #pragma unroll
        for (int nt = 0; nt < 8; nt++)
            #pragma unroll
            for (int q = 0; q < 4; q++) acc[mi][nt][q] = 0.0f;

    const int srow = tid >> 1;
    const int shalf = tid & 1;

    #pragma unroll 1
    for (int ph = 0; ph < 2; ph++) {
        {
            size_t src = (size_t)(gate * 128 + srow) * INDIM + ph * 64 + shalf * 32;
            const char* bh = (const char*)(g_whi + src);
            const char* bl = (const char*)(g_wlo + src);
            #pragma unroll
            for (int u = 0; u < 4; u++) {
                uint32_t o = swz128(srow, shalf * 4 + u);
                cp_async16(sbase + GXK_B_HI + o, bh + u * 16);
                cp_async16(sbase + GXK_B_LO + o, bl + u * 16);
            }
            asm volatile("cp.async.commit_group;" ::: "memory");
        }
        {
            const float4* xr = (const float4*)(x + (size_t)(m0g + srow) * INDIM
                                               + ph * 64 + shalf * 32);
            #pragma unroll
            for (int u = 0; u < 4; u++) {
                float4 a = xr[2 * u], b = xr[2 * u + 1];
                float f[8] = {a.x, a.y, a.z, a.w, b.x, b.y, b.z, b.w};
                uint32_t hi[4], lo[4];
                #pragma unroll
                for (int p = 0; p < 4; p++) {
                    __nv_bfloat162 h = __floats2bfloat162_rn(f[2*p], f[2*p+1]);
                    hi[p] = *(uint32_t*)&h;
                    float l0 = f[2*p]     - __bfloat162float(h.x);
                    float l1 = f[2*p + 1] - __bfloat162float(h.y);
                    __nv_bfloat162 l = __floats2bfloat162_rn(l0, l1);
                    lo[p] = *(uint32_t*)&l;
                }
                uint32_t o = swz128(srow, shalf * 4 + u);
                *(uint4*)(smemc + GXK_A_HI + o) = make_uint4(hi[0], hi[1], hi[2], hi[3]);
                *(uint4*)(smemc + GXK_A_LO + o) = make_uint4(lo[0], lo[1], lo[2], lo[3]);
            }
        }
        asm volatile("cp.async.wait_group 0;" ::: "memory");
        __syncthreads();

        #pragma unroll
        for (int s = 0; s < 4; s++) {
            const int c16 = 2 * s + lc;
            const int ra  = m0w + lr;

            uint32_t a0[4], a1[4];
            ldsm_x4(a0, sbase + GXK_A_HI + swz128(ra, c16));
            ldsm_x4(a1, sbase + GXK_A_HI + swz128(ra + 16, c16));

            uint32_t bh[4][4];
            #pragma unroll
            for (int q = 0; q < 4; q++)
                ldsm_x4(bh[q], sbase + GXK_B_HI + swz128(n0w + q * 16 + lr, c16));

            #pragma unroll
            for (int nt = 0; nt < 8; nt++) {
                int q = nt >> 1, sel = nt & 1;
                mma_bf16(acc[0][nt], a0, bh[q][sel], bh[q][sel + 2]);
                mma_bf16(acc[1][nt], a1, bh[q][sel], bh[q][sel + 2]);
            }
            {
                uint32_t bl[4][4];
                #pragma unroll
                for (int q = 0; q < 4; q++)
                    ldsm_x4(bl[q], sbase + GXK_B_LO + swz128(n0w + q * 16 + lr, c16));
                #pragma unroll
                for (int nt = 0; nt < 8; nt++) {
                    int q = nt >> 1, sel = nt & 1;
                    mma_bf16(acc[0][nt], a0, bl[q][sel], bl[q][sel + 2]);
                    mma_bf16(acc[1][nt], a1, bl[q][sel], bl[q][sel + 2]);
                }
            }
            {
                uint32_t l0[4], l1[4];
                ldsm_x4(l0, sbase + GXK_A_LO + swz128(ra, c16));
                ldsm_x4(l1, sbase + GXK_A_LO + swz128(ra + 16, c16));
                #pragma unroll
                for (int nt = 0; nt < 8; nt++) {
                    int q = nt >> 1, sel = nt & 1;
                    mma_bf16(acc[0][nt], l0, bh[q][sel], bh[q][sel + 2]);
                    mma_bf16(acc[1][nt], l1, bh[q][sel], bh[q][sel + 2]);
                }
            }
        }
        if (ph == 0) __syncthreads();
    }

    const int colq = (lane & 3) * 2;
    #pragma unroll
    for (int nt = 0; nt < 8; nt++) {
        int c = n0w + nt * 8 + colq;
        float2 bv = *(const float2*)(bvec + gate * 128 + c);
        #pragma unroll
        for (int mi = 0; mi < 2; mi++) {
            int gm0 = m0g + m0w + 16 * mi + (lane >> 2);
            #pragma unroll
            for (int h = 0; h < 2; h++) {
                int gm = gm0 + 8 * h;
                int tt = gm & 255, bb = gm >> 8;
                float2 o;
                o.x = acc[mi][nt][2 * h + 0] + bv.x;
                o.y = acc[mi][nt][2 * h + 1] + bv.y;
                *(float2*)(g_gx + ((size_t)tt * BB + bb) * GG + gate * 128 + c) = o;
            }
        }
    }
}

// ============================================================================
// Kernel 4 (v8 = rec_tc): TENSOR-CORE recurrence. 128 CTAs x 512 threads,
// 8 batch rows/CTA. w_h^T bf16 hi/lo staged in smem ONCE (192KB, static).
// Per step: zr = h[8x128] @ whh[:, :256]  (3-term bf16 split, M padded to 16,
// garbage rows 8-15 land only in unread acc slots), then a-gate on rh.
// h fp32 master in smem; h and rh re-split to bf16 per step. 2 barriers/step.
// Warp layout: zr: warp w owns n-cols [16w,16w+16); a: cols [8w, 8w+8).
// ============================================================================
#define RT_B_HI  0          // 384*256 = 98304
#define RT_B_LO  98304
#define RT_HHI   196608     // 16x128 bf16 = 4096
#define RT_HLO   200704
#define RT_RHHI  204800
#define RT_RHLO  208896
#define RT_H32   212992     // 8*128 f32 = 4096
#define RT_ZS    217088     // 128*8 f32 = 4096
#define RT_SMEM  221184

__global__ void __launch_bounds__(512, 1) rec_tc_kernel()
{
    extern __shared__ char smemc[];
    uint32_t sb = smem_u32(smemc);
    float* h32 = (float*)(smemc + RT_H32);
    float* zsf = (float*)(smemc + RT_ZS);
    const int tid  = threadIdx.x;
    const int wid  = tid >> 5;
    const int lane = tid & 31;
    const int b0   = blockIdx.x * 8;

    // ---- stage static B = whh hi/lo, swizzled (rows 384 x 256B) ----
    for (int idx = tid; idx < 384 * 16; idx += 512) {
        int r = idx >> 4, c = idx & 15;
        uint32_t o = swz(r, c);
        cp_async16(sb + RT_B_HI + o, (const char*)g_whh_hi + (size_t)r * 256 + c * 16);
        cp_async16(sb + RT_B_LO + o, (const char*)g_whh_lo + (size_t)r * 256 + c * 16);
    }
    asm volatile("cp.async.commit_group;" ::: "memory");
    // zero h/rh tiles (incl. pad rows 8-15) and h32
    for (int idx = tid; idx < 1024; idx += 512) {
        ((uint32_t*)(smemc + RT_HHI))[idx]  = 0;
        ((uint32_t*)(smemc + RT_HLO))[idx]  = 0;
        ((uint32_t*)(smemc + RT_RHHI))[idx] = 0;
        ((uint32_t*)(smemc + RT_RHLO))[idx] = 0;
        h32[idx] = 0.0f;
    }
    asm volatile("cp.async.wait_group 0;" ::: "memory");
    __syncthreads();

    const int lr   = lane & 15;
    const int lc   = lane >> 4;
    const int row  = lane >> 2;          // 0..7 (batch row)
    const int cp2  = 2 * (lane & 3);     // col pair base
    const int n0z  = wid * 16;           // zr B-row base (cols of gates z|r)
    const int n0a  = 256 + wid * 8;      // a-gate B-row base
    const int acol = wid * 8 + cp2;      // a-gate output col (0..127)
    const int jz   = n0z - 128;          // r-warp j base (warps 8..15)

    for (int t = 0; t < TT; t++) {
        const float* gxt = g_gx + ((size_t)t * BB + b0) * GG;
        // prefetch gx for epilogues (covered by mma loops)
        float2 gz0 = *(const float2*)(gxt + row * GG + n0z + cp2);
        float2 gz1 = *(const float2*)(gxt + row * GG + n0z + 8 + cp2);
        float2 ga  = *(const float2*)(gxt + row * GG + 256 + acol);

        // ---- zr MMA: [16(pad)x128] @ [128 x n16-slice], 3-term split ----
        float az[2][4];
        #pragma unroll
        for (int nt = 0; nt < 2; nt++)
            #pragma unroll
            for (int q = 0; q < 4; q++) az[nt][q] = 0.0f;

        #pragma unroll
        for (int s = 0; s < 8; s++) {
            int c16 = 2 * s + lc;
            uint32_t ah[4], al[4], bh[4], bl[4];
            ldsm_x4(ah, sb + RT_HHI  + swz(lr, c16));
            ldsm_x4(al, sb + RT_HLO  + swz(lr, c16));
            ldsm_x4(bh, sb + RT_B_HI + swz(n0z + lr, c16));
            ldsm_x4(bl, sb + RT_B_LO + swz(n0z + lr, c16));
            #pragma unroll
            for (int nt = 0; nt < 2; nt++) {
                mma_bf16(az[nt], ah, bh[nt], bh[nt + 2]);
                mma_bf16(az[nt], ah, bl[nt], bl[nt + 2]);
                mma_bf16(az[nt], al, bh[nt], bh[nt + 2]);
            }
        }
        {
            float v00 = az[0][0] + gz0.x, v01 = az[0][1] + gz0.y;
            float v10 = az[1][0] + gz1.x, v11 = az[1][1] + gz1.y;
            if (wid < 8) {                       // z gate: cols n0z..n0z+15
                zsf[(n0z + cp2)         * 8 + row] = sigmoid_f(v00);
                zsf[(n0z + cp2 + 1)     * 8 + row] = sigmoid_f(v01);
                zsf[(n0z + 8 + cp2)     * 8 + row] = sigmoid_f(v10);
                zsf[(n0z + 8 + cp2 + 1) * 8 + row] = sigmoid_f(v11);
            } else {                             // r gate -> rh = r .* h
                float2 h0 = *(const float2*)&h32[row * 128 + jz + cp2];
                float2 h1 = *(const float2*)&h32[row * 128 + jz + 8 + cp2];
                float r00 = sigmoid_f(v00) * h0.x, r01 = sigmoid_f(v01) * h0.y;
                float r10 = sigmoid_f(v10) * h1.x, r11 = sigmoid_f(v11) * h1.y;
                bsplit_store(smemc, RT_RHHI, RT_RHLO, row, jz + cp2,     r00, r01);
                bsplit_store(smemc, RT_RHHI, RT_RHLO, row, jz + 8 + cp2, r10, r11);
            }
        }
        __syncthreads();

        // ---- a-gate MMA: rh[16(pad)x128] @ [128 x n8-slice], 3-term ----
        float aa[4] = {0.0f, 0.0f, 0.0f, 0.0f};
        #pragma unroll
        for (int s = 0; s < 8; s++) {
            int c16 = 2 * s + lc;
            uint32_t rh_[4], rl_[4], bh[4], bl[4];
            ldsm_x4(rh_, sb + RT_RHHI + swz(lr, c16));
            ldsm_x4(rl_, sb + RT_RHLO + swz(lr, c16));
            ldsm_x4(bh,  sb + RT_B_HI + swz(n0a + lr, c16));  // w=15 overreads into B_LO: unused tiles
            ldsm_x4(bl,  sb + RT_B_LO + swz(n0a + lr, c16));  // overreads into h tiles: unused tiles
            mma_bf16(aa, rh_, bh[0], bh[2]);
            mma_bf16(aa, rh_, bl[0], bl[2]);
            mma_bf16(aa, rl_, bh[0], bh[2]);
        }
        {
            float a0 = tanh_f(aa[0] + ga.x);
            float a1 = tanh_f(aa[1] + ga.y);
            float z0 = zsf[(acol)     * 8 + row];
            float z1 = zsf[(acol + 1) * 8 + row];
            float2 hv = *(const float2*)&h32[row * 128 + acol];
            float hn0 = fmaf(z0, a0 - hv.x, hv.x);
            float hn1 = fmaf(z1, a1 - hv.y, hv.y);
            *(float2*)&h32[row * 128 + acol] = make_float2(hn0, hn1);
            bsplit_store(smemc, RT_HHI, RT_HLO, row, acol, hn0, hn1);
            *(float2*)&g_ys[((size_t)t * BB + b0 + row) * HH + acol] = make_float2(hn0, hn1);
        }
        __syncthreads();
    }
}

// ============================================================================
// Kernel 5 (unchanged): out[b,p] = sum_t sum_j ys[t,b,j]*W2[t,j,p] + bias.
// ============================================================================
__global__ void __launch_bounds__(512, 1) fc_kernel(float* __restrict__ out)
{
    __shared__ float red[8 * HOR * 4];

    const int tid = threadIdx.x;
    const int j   = tid & 127;
    const int g   = tid >> 7;
    const int b0  = blockIdx.x * 8;
    const int lane = tid & 31;
    const int jblk = (j >> 5);

    u64 acc[2][12];
    #pragma unroll
    for (int u = 0; u < 2; u++)
        #pragma unroll
        for (int q = 0; q < 12; q++) acc[u][q] = 0ULL;

    #pragma unroll 2
    for (int t = 0; t < TT; t++) {
        const float* ysp = g_ys + ((size_t)t * BB + b0 + 2 * g) * HH + j;
        float y0 = __ldg(ysp);
        float y1 = __ldg(ysp + HH);
        const ulonglong2* wp = (const ulonglong2*)(g_W2 + ((size_t)t * HH + j) * HOR);
        ulonglong2 w0 = wp[0], w1 = wp[1], w2 = wp[2],
                   w3 = wp[3], w4 = wp[4], w5 = wp[5];
        u64 wq[12] = {w0.x, w0.y, w1.x, w1.y, w2.x, w2.y,
                      w3.x, w3.y, w4.x, w4.y, w5.x, w5.y};
        u64 y0d = dup2(y0), y1d = dup2(y1);
        #pragma unroll
        for (int q = 0; q < 12; q++) {
            ffma2(acc[0][q], y0d, wq[q]);
            ffma2(acc[1][q], y1d, wq[q]);
        }
    }

    #pragma unroll
    for (int u = 0; u < 2; u++)
        #pragma unroll
        for (int q = 0; q < 12; q++) {
            fadd2(acc[u][q], shfl_xor_u64(acc[u][q], 1));
            fadd2(acc[u][q], shfl_xor_u64(acc[u][q], 2));
            fadd2(acc[u][q], shfl_xor_u64(acc[u][q], 4));
            fadd2(acc[u][q], shfl_xor_u64(acc[u][q], 8));
            fadd2(acc[u][q], shfl_xor_u64(acc[u][q], 16));
        }

    if (lane == 0) {
        #pragma unroll
        for (int u = 0; u < 2; u++) {
            int rrow = 2 * g + u;
            #pragma unroll
            for (int q = 0; q < 12; q++) {
                float v0, v1;
                unpack2(acc[u][q], v0, v1);
                red[(rrow * HOR + 2 * q + 0) * 4 + jblk] = v0;
                red[(rrow * HOR + 2 * q + 1) * 4 + jblk] = v1;
            }
        }
    }
    __syncthreads();

    if (tid < 8 * HOR) {
        int rrow = tid / HOR;
        int p    = tid - rrow * HOR;
        const float* pp = red + (rrow * HOR + p) * 4;
        float s = ((pp[0] + pp[1]) + pp[2]) + pp[3];
        out[(size_t)(b0 + rrow) * HOR + p] = s + g_final_bias[p];
    }
}

// ============================================================================
// launch
// ============================================================================
extern "C" void kernel_launch(void* const* d_in, const int* in_sizes, int n_in,
                              void* d_out, int out_size)
{
    const float* x     = (const float*)d_in[0];
    const float* w_i   = (const float*)d_in[1];
    const float* w_h   = (const float*)d_in[2];
    const float* bvec  = (const float*)d_in[3];
    const float* mlp_w = (const float*)d_in[4];
    const float* mlp_b = (const float*)d_in[5];
    const float* fc_w  = (const float*)d_in[6];
    const float* fc_b  = (const float*)d_in[7];
    const float* out_w = (const float*)d_in[8];
    const float* out_b = (const float*)d_in[9];
    float* out = (float*)d_out;

    const int smem_w2 = (3072 + 12288 + 1024) * 4;   // 65536

    cudaFuncSetAttribute(w2_kernel,     cudaFuncAttributeMaxDynamicSharedMemorySize, smem_w2);
    cudaFuncSetAttribute(gx_mma_kernel, cudaFuncAttributeMaxDynamicSharedMemorySize, GXK_SMEM);
    cudaFuncSetAttribute(rec_tc_kernel, cudaFuncAttributeMaxDynamicSharedMemorySize, RT_SMEM);

    w2_kernel<<<TT, 256, smem_w2>>>(mlp_w, mlp_b, fc_w, out_w);
    bias_final_kernel<<<1, 32>>>(fc_b, out_w, out_b);
    wsplit_kernel<<<GG, 128>>>(w_i);
    whhsplit_kernel<<<GG, 128>>>(w_h);
    gx_mma_kernel<<<(BB * TT / 128) * 3, 256, GXK_SMEM>>>(x, bvec);
    rec_tc_kernel<<<BB / 8, 512, RT_SMEM>>>();
    fc_kernel<<<BB / 8, 512>>>(out);
}